// round 3
// baseline (speedup 1.0000x reference)
#include <cuda_runtime.h>
#include <math.h>

#define BATCH   2
#define SEQ     2048
#define DMODEL  2048
#define NHEADS  16
#define DHEAD   128

// Scratch (allocation-free: __device__ globals)
__device__ float g_Q[BATCH*NHEADS*SEQ*DHEAD];   // [B][H][S][Dh]
__device__ float g_K[BATCH*NHEADS*SEQ*DHEAD];
__device__ float g_V[BATCH*NHEADS*SEQ*DHEAD];
__device__ float g_Z[BATCH*SEQ*NHEADS*DHEAD];   // [B][S][H][Dh]

// ---------------------------------------------------------------------------
// tf32 + fragment-layout helpers
// ---------------------------------------------------------------------------
__device__ __forceinline__ unsigned f2tf32(float x) {
    unsigned y;
    asm("cvt.rna.tf32.f32 %0, %1;" : "=r"(y) : "f"(x));
    return y;
}

__device__ __forceinline__ void mma_tf32(float* c, const unsigned* a, const unsigned* b) {
    asm volatile(
        "mma.sync.aligned.m16n8k8.row.col.f32.tf32.tf32.f32 "
        "{%0,%1,%2,%3}, {%4,%5,%6,%7}, {%8,%9}, {%0,%1,%2,%3};\n"
        : "+f"(c[0]), "+f"(c[1]), "+f"(c[2]), "+f"(c[3])
        : "r"(a[0]), "r"(a[1]), "r"(a[2]), "r"(a[3]), "r"(b[0]), "r"(b[1]));
}

// A-fragment layout for m16k8 tiles: element (m,k) of a [M x K] tile.
// block (m>>4, k>>3), lane=(m&7)*4+(k&3), reg = (m&8)>>3 | ((k&4)>>2)<<1.
// Storage: ((mt*Kq + kt)*32 + lane)*4 + reg  -> compute loads one uint4/lane.
__device__ __forceinline__ int afrag(int m, int k, int Kq) {
    return ((((m >> 4) * Kq + (k >> 3)) * 32 + (m & 7) * 4 + (k & 3)) << 2)
           + (((k & 4) >> 1) | ((m & 8) >> 3));
}
// B-fragment layout for n8k8 tiles (col-major B): element (k,n).
// lane=(n&7)*4+(k&3), reg=(k&4)>>2.  Storage: ((kt*Nq+nt)*32+lane)*2+reg.
__device__ __forceinline__ int bfrag(int k, int n, int Nq) {
    return ((((k >> 3) * Nq + (n >> 3)) * 32 + (n & 7) * 4 + (k & 3)) << 1)
           + ((k & 4) >> 2);
}

// ---------------------------------------------------------------------------
// Phase 1: QKV projection (tf32, fragment smem, reg-prefetch pipeline).
// grid = (16 heads, 32 m-tiles, 3 {Q,K,V}); 8 warps: warpM{0,1} x warpN{0..3};
// block tile 128x128, k-slab 32, warp tile 64x32.
// ---------------------------------------------------------------------------
__global__ __launch_bounds__(256) void qkv_gemm_tc(
    const float* __restrict__ X,
    const float* __restrict__ Wq, const float* __restrict__ Wk, const float* __restrict__ Wv,
    const float* __restrict__ bq, const float* __restrict__ bk, const float* __restrict__ bv)
{
    __shared__ __align__(16) unsigned As[128 * 32];   // A-frag, Kq=4
    __shared__ __align__(16) unsigned Bs[32 * 128];   // B-frag, Nq=16

    const float* W; const float* bias; float* out;
    if (blockIdx.z == 0)      { W = Wq; bias = bq; out = g_Q; }
    else if (blockIdx.z == 1) { W = Wk; bias = bk; out = g_K; }
    else                      { W = Wv; bias = bv; out = g_V; }

    const int h   = blockIdx.x;
    const int m0  = blockIdx.y * 128;
    const int tid = threadIdx.x;
    const int warp = tid >> 5, lane = tid & 31;
    const int warpM = warp >> 2, warpN = warp & 3;
    const int lq = lane >> 2, lr = lane & 3;
    const float* Wh = W + (size_t)h * DMODEL * DHEAD;

    const int arow = tid >> 3, acol = (tid & 7) * 4;    // A stage coords (x4 iters)
    const int brow = tid >> 5, bcol = (tid & 31) * 4;   // B stage coords (x4 iters)

    float c[4][4][4];
    #pragma unroll
    for (int mi = 0; mi < 4; mi++)
        #pragma unroll
        for (int ni = 0; ni < 4; ni++)
            #pragma unroll
            for (int j = 0; j < 4; j++) c[mi][ni][j] = 0.f;

    float4 pa[4], pb[4];
    // prologue: load + store slab 0
    #pragma unroll
    for (int i = 0; i < 4; i++) {
        pa[i] = *(const float4*)(X + (size_t)(m0 + arow + i * 32) * DMODEL + acol);
        pb[i] = *(const float4*)(Wh + (size_t)(brow + i * 8) * DHEAD + bcol);
    }
    #pragma unroll
    for (int i = 0; i < 4; i++) {
        int r = arow + i * 32;
        As[afrag(r, acol + 0, 4)] = f2tf32(pa[i].x);
        As[afrag(r, acol + 1, 4)] = f2tf32(pa[i].y);
        As[afrag(r, acol + 2, 4)] = f2tf32(pa[i].z);
        As[afrag(r, acol + 3, 4)] = f2tf32(pa[i].w);
        int kr = brow + i * 8;
        Bs[bfrag(kr, bcol + 0, 16)] = f2tf32(pb[i].x);
        Bs[bfrag(kr, bcol + 1, 16)] = f2tf32(pb[i].y);
        Bs[bfrag(kr, bcol + 2, 16)] = f2tf32(pb[i].z);
        Bs[bfrag(kr, bcol + 3, 16)] = f2tf32(pb[i].w);
    }

    for (int k0 = 0; k0 < DMODEL; k0 += 32) {
        __syncthreads();
        const bool has_next = (k0 + 32) < DMODEL;
        if (has_next) {
            #pragma unroll
            for (int i = 0; i < 4; i++) {
                pa[i] = *(const float4*)(X + (size_t)(m0 + arow + i * 32) * DMODEL + k0 + 32 + acol);
                pb[i] = *(const float4*)(Wh + (size_t)(k0 + 32 + brow + i * 8) * DHEAD + bcol);
            }
        }
        // compute slab
        #pragma unroll
        for (int kt = 0; kt < 4; kt++) {
            uint4 a[4]; uint2 b[4];
            #pragma unroll
            for (int mi = 0; mi < 4; mi++)
                a[mi] = ((const uint4*)As)[((warpM * 4 + mi) * 4 + kt) * 32 + lane];
            #pragma unroll
            for (int ni = 0; ni < 4; ni++)
                b[ni] = ((const uint2*)Bs)[(kt * 16 + warpN * 4 + ni) * 32 + lane];
            #pragma unroll
            for (int mi = 0; mi < 4; mi++)
                #pragma unroll
                for (int ni = 0; ni < 4; ni++)
                    mma_tf32(c[mi][ni], (const unsigned*)&a[mi], (const unsigned*)&b[ni]);
        }
        __syncthreads();
        if (has_next) {
            #pragma unroll
            for (int i = 0; i < 4; i++) {
                int r = arow + i * 32;
                As[afrag(r, acol + 0, 4)] = f2tf32(pa[i].x);
                As[afrag(r, acol + 1, 4)] = f2tf32(pa[i].y);
                As[afrag(r, acol + 2, 4)] = f2tf32(pa[i].z);
                As[afrag(r, acol + 3, 4)] = f2tf32(pa[i].w);
                int kr = brow + i * 8;
                Bs[bfrag(kr, bcol + 0, 16)] = f2tf32(pb[i].x);
                Bs[bfrag(kr, bcol + 1, 16)] = f2tf32(pb[i].y);
                Bs[bfrag(kr, bcol + 2, 16)] = f2tf32(pb[i].z);
                Bs[bfrag(kr, bcol + 3, 16)] = f2tf32(pb[i].w);
            }
        }
    }

    // epilogue (C-fragment coords)
    #pragma unroll
    for (int mi = 0; mi < 4; mi++) {
        #pragma unroll
        for (int half = 0; half < 2; half++) {
            int m = m0 + warpM * 64 + mi * 16 + lq + half * 8;
            int b_ = m >> 11, s = m & 2047;
            float* orow = out + (((size_t)(b_ * NHEADS + h)) * SEQ + s) * DHEAD;
            #pragma unroll
            for (int ni = 0; ni < 4; ni++) {
                int n = warpN * 32 + ni * 8 + 2 * lr;
                float2 r;
                r.x = c[mi][ni][half * 2 + 0] + bias[h * DHEAD + n];
                r.y = c[mi][ni][half * 2 + 1] + bias[h * DHEAD + n + 1];
                *(float2*)(orow + n) = r;
            }
        }
    }
}

// ---------------------------------------------------------------------------
// Phase 2: causal flash attention (tf32, fragment smem).
// grid = (32 q-tiles, B*H), 8 warps: warpR{0..3} x warpC{0,1}.
// ---------------------------------------------------------------------------
#define AOFF_KV 8192                 // Qs: A-frag 64x128 (Kq=16)
#define AOFF_P  (AOFF_KV + 8192)     // KVs: B-frag (K:128x64 Nq=8 / V:64x128 Nq=16)
#define AOFF_MX (AOFF_P + 4096)      // Ps: A-frag 64x64 (Kq=8)
#define AOFF_SM (AOFF_MX + 128)
#define ATT_SMEM_BYTES ((AOFF_SM + 128) * 4)   // 82944

__global__ __launch_bounds__(256, 2) void attn_tc()
{
    extern __shared__ __align__(16) unsigned smu[];
    unsigned* Qs  = smu;
    unsigned* KVs = smu + AOFF_KV;
    unsigned* Ps  = smu + AOFF_P;
    float* smax = (float*)(smu + AOFF_MX);   // [2][64]
    float* ssum = (float*)(smu + AOFF_SM);   // [2][64]

    const int tid = threadIdx.x;
    const int warp = tid >> 5, lane = tid & 31;
    const int warpR = warp >> 1, warpC = warp & 1;
    const int lq = lane >> 2, lr = lane & 3;
    const int bh = blockIdx.y;
    const int b  = bh >> 4, h = bh & 15;
    const int q0 = blockIdx.x * 64;
    const int r_loc = warpR * 16 + lq;

    const float* Qg = g_Q + (size_t)(b * NHEADS + h) * SEQ * DHEAD;
    const float* Kg = g_K + (size_t)(b * NHEADS + h) * SEQ * DHEAD;
    const float* Vg = g_V + (size_t)(b * NHEADS + h) * SEQ * DHEAD;

    const float scale = 0.08838834764831845f;  // 1/sqrt(128), folded into Q
    const int srow = tid >> 5, scol = (tid & 31) * 4;   // stage coords (x8 iters of 8 rows)

    // load Q tile 64x128, scaled, A-frag layout (Kq=16)
    #pragma unroll
    for (int i = 0; i < 8; i++) {
        int row = srow + i * 8;
        float4 v = *(const float4*)(Qg + (size_t)(q0 + row) * DHEAD + scol);
        Qs[afrag(row, scol + 0, 16)] = f2tf32(v.x * scale);
        Qs[afrag(row, scol + 1, 16)] = f2tf32(v.y * scale);
        Qs[afrag(row, scol + 2, 16)] = f2tf32(v.z * scale);
        Qs[afrag(row, scol + 3, 16)] = f2tf32(v.w * scale);
    }

    float o[8][4];
    #pragma unroll
    for (int ni = 0; ni < 8; ni++)
        #pragma unroll
        for (int j = 0; j < 4; j++) o[ni][j] = 0.f;
    float m0v = -INFINITY, m1v = -INFINITY, l0 = 0.f, l1 = 0.f;

    const int ntiles = blockIdx.x + 1;   // causal tile skipping

    for (int kt2 = 0; kt2 < ntiles; kt2++) {
        const int k0t = kt2 * 64;
        __syncthreads();   // prev PV done with KVs; Q visible on first iter
        // K tile (64 keys x 128 dh) -> B-frag over (k=dh, n=key), Nq=8
        #pragma unroll
        for (int i = 0; i < 8; i++) {
            int key = srow + i * 8;
            float4 v = *(const float4*)(Kg + (size_t)(k0t + key) * DHEAD + scol);
            KVs[bfrag(scol + 0, key, 8)] = f2tf32(v.x);
            KVs[bfrag(scol + 1, key, 8)] = f2tf32(v.y);
            KVs[bfrag(scol + 2, key, 8)] = f2tf32(v.z);
            KVs[bfrag(scol + 3, key, 8)] = f2tf32(v.w);
        }
        __syncthreads();

        // S = Q K^T : warp 16x32, k=128
        float s[4][4];
        #pragma unroll
        for (int ni = 0; ni < 4; ni++)
            #pragma unroll
            for (int j = 0; j < 4; j++) s[ni][j] = 0.f;

        #pragma unroll
        for (int kt = 0; kt < 16; kt++) {
            uint4 a = ((const uint4*)Qs)[(warpR * 16 + kt) * 32 + lane];
            #pragma unroll
            for (int ni = 0; ni < 4; ni++) {
                uint2 bb = ((const uint2*)KVs)[(kt * 8 + warpC * 4 + ni) * 32 + lane];
                mma_tf32(s[ni], (const unsigned*)&a, (const unsigned*)&bb);
            }
        }

        // causal mask + row max
        const int r0g = q0 + r_loc, r1g = r0g + 8;
        float mx0 = -1e30f, mx1 = -1e30f;
        #pragma unroll
        for (int ni = 0; ni < 4; ni++) {
            int cb = k0t + warpC * 32 + ni * 8 + 2 * lr;
            if (cb     > r0g) s[ni][0] = -1e30f;
            if (cb + 1 > r0g) s[ni][1] = -1e30f;
            if (cb     > r1g) s[ni][2] = -1e30f;
            if (cb + 1 > r1g) s[ni][3] = -1e30f;
            mx0 = fmaxf(mx0, fmaxf(s[ni][0], s[ni][1]));
            mx1 = fmaxf(mx1, fmaxf(s[ni][2], s[ni][3]));
        }
        mx0 = fmaxf(mx0, __shfl_xor_sync(0xffffffffu, mx0, 1));
        mx0 = fmaxf(mx0, __shfl_xor_sync(0xffffffffu, mx0, 2));
        mx1 = fmaxf(mx1, __shfl_xor_sync(0xffffffffu, mx1, 1));
        mx1 = fmaxf(mx1, __shfl_xor_sync(0xffffffffu, mx1, 2));
        if (lr == 0) {
            smax[warpC * 64 + r_loc]     = mx0;
            smax[warpC * 64 + r_loc + 8] = mx1;
        }
        __syncthreads();   // all warps done with K reads too
        mx0 = fmaxf(mx0, smax[(warpC ^ 1) * 64 + r_loc]);
        mx1 = fmaxf(mx1, smax[(warpC ^ 1) * 64 + r_loc + 8]);

        float mn0 = fmaxf(m0v, mx0), mn1 = fmaxf(m1v, mx1);
        float ef0 = __expf(m0v - mn0), ef1 = __expf(m1v - mn1);
        m0v = mn0; m1v = mn1;

        float sum0 = 0.f, sum1 = 0.f;
        #pragma unroll
        for (int ni = 0; ni < 4; ni++) {
            float p0 = __expf(s[ni][0] - mn0);
            float p1 = __expf(s[ni][1] - mn0);
            float p2 = __expf(s[ni][2] - mn1);
            float p3 = __expf(s[ni][3] - mn1);
            sum0 += p0 + p1; sum1 += p2 + p3;
            int kc2 = warpC * 32 + ni * 8 + 2 * lr;
            Ps[afrag(r_loc,     kc2,     8)] = f2tf32(p0);
            Ps[afrag(r_loc,     kc2 + 1, 8)] = f2tf32(p1);
            Ps[afrag(r_loc + 8, kc2,     8)] = f2tf32(p2);
            Ps[afrag(r_loc + 8, kc2 + 1, 8)] = f2tf32(p3);
        }
        sum0 += __shfl_xor_sync(0xffffffffu, sum0, 1);
        sum0 += __shfl_xor_sync(0xffffffffu, sum0, 2);
        sum1 += __shfl_xor_sync(0xffffffffu, sum1, 1);
        sum1 += __shfl_xor_sync(0xffffffffu, sum1, 2);
        if (lr == 0) {
            ssum[warpC * 64 + r_loc]     = sum0;
            ssum[warpC * 64 + r_loc + 8] = sum1;
        }
        // rescale O accumulator
        #pragma unroll
        for (int ni = 0; ni < 8; ni++) {
            o[ni][0] *= ef0; o[ni][1] *= ef0;
            o[ni][2] *= ef1; o[ni][3] *= ef1;
        }
        // V tile (64 keys x 128 e) -> B-frag over (k=key, n=e), Nq=16
        #pragma unroll
        for (int i = 0; i < 8; i++) {
            int key = srow + i * 8;
            float4 v = *(const float4*)(Vg + (size_t)(k0t + key) * DHEAD + scol);
            KVs[bfrag(key, scol + 0, 16)] = f2tf32(v.x);
            KVs[bfrag(key, scol + 1, 16)] = f2tf32(v.y);
            KVs[bfrag(key, scol + 2, 16)] = f2tf32(v.z);
            KVs[bfrag(key, scol + 3, 16)] = f2tf32(v.w);
        }
        __syncthreads();   // Ps + V + ssum visible

        l0 = l0 * ef0 + sum0 + ssum[(warpC ^ 1) * 64 + r_loc];
        l1 = l1 * ef1 + sum1 + ssum[(warpC ^ 1) * 64 + r_loc + 8];

        // O += P @ V : warp 16x64, k=64
        #pragma unroll
        for (int kt = 0; kt < 8; kt++) {
            uint4 a = ((const uint4*)Ps)[(warpR * 8 + kt) * 32 + lane];
            #pragma unroll
            for (int ni = 0; ni < 8; ni++) {
                uint2 bb = ((const uint2*)KVs)[(kt * 16 + warpC * 8 + ni) * 32 + lane];
                mma_tf32(o[ni], (const unsigned*)&a, (const unsigned*)&bb);
            }
        }
    }

    // normalize + write Z in [B][S][H][Dh]
    float inv0 = 1.f / l0, inv1 = 1.f / l1;
    const int q_0 = q0 + r_loc;
    #pragma unroll
    for (int ni = 0; ni < 8; ni++) {
        int e = warpC * 64 + ni * 8 + 2 * lr;
        float2 z0; z0.x = o[ni][0] * inv0; z0.y = o[ni][1] * inv0;
        float2 z1; z1.x = o[ni][2] * inv1; z1.y = o[ni][3] * inv1;
        *(float2*)(g_Z + (((size_t)(b * SEQ + q_0)) * NHEADS + h) * DHEAD + e)     = z0;
        *(float2*)(g_Z + (((size_t)(b * SEQ + q_0 + 8)) * NHEADS + h) * DHEAD + e) = z1;
    }
}

// ---------------------------------------------------------------------------
// Phase 3: output projection (tf32, fragment smem, reg-prefetch pipeline).
// grid = (16 n-tiles, 32 m-tiles), block tile 128x128, k-slab 32.
// ---------------------------------------------------------------------------
__global__ __launch_bounds__(256) void out_gemm_tc(
    const float* __restrict__ WO, const float* __restrict__ bO,
    float* __restrict__ out)
{
    __shared__ __align__(16) unsigned As[128 * 32];
    __shared__ __align__(16) unsigned Bs[32 * 128];

    const int n0  = blockIdx.x * 128;
    const int m0  = blockIdx.y * 128;
    const int tid = threadIdx.x;
    const int warp = tid >> 5, lane = tid & 31;
    const int warpM = warp >> 2, warpN = warp & 3;
    const int lq = lane >> 2, lr = lane & 3;

    const int arow = tid >> 3, acol = (tid & 7) * 4;
    const int brow = tid >> 5, bcol = (tid & 31) * 4;

    float c[4][4][4];
    #pragma unroll
    for (int mi = 0; mi < 4; mi++)
        #pragma unroll
        for (int ni = 0; ni < 4; ni++)
            #pragma unroll
            for (int j = 0; j < 4; j++) c[mi][ni][j] = 0.f;

    float4 pa[4], pb[4];
    #pragma unroll
    for (int i = 0; i < 4; i++) {
        pa[i] = *(const float4*)(g_Z + (size_t)(m0 + arow + i * 32) * DMODEL + acol);
        pb[i] = *(const float4*)(WO + (size_t)(brow + i * 8) * DMODEL + n0 + bcol);
    }
    #pragma unroll
    for (int i = 0; i < 4; i++) {
        int r = arow + i * 32;
        As[afrag(r, acol + 0, 4)] = f2tf32(pa[i].x);
        As[afrag(r, acol + 1, 4)] = f2tf32(pa[i].y);
        As[afrag(r, acol + 2, 4)] = f2tf32(pa[i].z);
        As[afrag(r, acol + 3, 4)] = f2tf32(pa[i].w);
        int kr = brow + i * 8;
        Bs[bfrag(kr, bcol + 0, 16)] = f2tf32(pb[i].x);
        Bs[bfrag(kr, bcol + 1, 16)] = f2tf32(pb[i].y);
        Bs[bfrag(kr, bcol + 2, 16)] = f2tf32(pb[i].z);
        Bs[bfrag(kr, bcol + 3, 16)] = f2tf32(pb[i].w);
    }

    for (int k0 = 0; k0 < DMODEL; k0 += 32) {
        __syncthreads();
        const bool has_next = (k0 + 32) < DMODEL;
        if (has_next) {
            #pragma unroll
            for (int i = 0; i < 4; i++) {
                pa[i] = *(const float4*)(g_Z + (size_t)(m0 + arow + i * 32) * DMODEL + k0 + 32 + acol);
                pb[i] = *(const float4*)(WO + (size_t)(k0 + 32 + brow + i * 8) * DMODEL + n0 + bcol);
            }
        }
        #pragma unroll
        for (int kt = 0; kt < 4; kt++) {
            uint4 a[4]; uint2 b[4];
            #pragma unroll
            for (int mi = 0; mi < 4; mi++)
                a[mi] = ((const uint4*)As)[((warpM * 4 + mi) * 4 + kt) * 32 + lane];
            #pragma unroll
            for (int ni = 0; ni < 4; ni++)
                b[ni] = ((const uint2*)Bs)[(kt * 16 + warpN * 4 + ni) * 32 + lane];
            #pragma unroll
            for (int mi = 0; mi < 4; mi++)
                #pragma unroll
                for (int ni = 0; ni < 4; ni++)
                    mma_tf32(c[mi][ni], (const unsigned*)&a[mi], (const unsigned*)&b[ni]);
        }
        __syncthreads();
        if (has_next) {
            #pragma unroll
            for (int i = 0; i < 4; i++) {
                int r = arow + i * 32;
                As[afrag(r, acol + 0, 4)] = f2tf32(pa[i].x);
                As[afrag(r, acol + 1, 4)] = f2tf32(pa[i].y);
                As[afrag(r, acol + 2, 4)] = f2tf32(pa[i].z);
                As[afrag(r, acol + 3, 4)] = f2tf32(pa[i].w);
                int kr = brow + i * 8;
                Bs[bfrag(kr, bcol + 0, 16)] = f2tf32(pb[i].x);
                Bs[bfrag(kr, bcol + 1, 16)] = f2tf32(pb[i].y);
                Bs[bfrag(kr, bcol + 2, 16)] = f2tf32(pb[i].z);
                Bs[bfrag(kr, bcol + 3, 16)] = f2tf32(pb[i].w);
            }
        }
    }

    #pragma unroll
    for (int mi = 0; mi < 4; mi++) {
        #pragma unroll
        for (int half = 0; half < 2; half++) {
            int m = m0 + warpM * 64 + mi * 16 + lq + half * 8;
            float* orow = out + (size_t)m * DMODEL + n0;
            #pragma unroll
            for (int ni = 0; ni < 4; ni++) {
                int n = warpN * 32 + ni * 8 + 2 * lr;
                float2 r;
                r.x = c[mi][ni][half * 2 + 0] + bO[n0 + n];
                r.y = c[mi][ni][half * 2 + 1] + bO[n0 + n + 1];
                *(float2*)(orow + n) = r;
            }
        }
    }
}

// ---------------------------------------------------------------------------
extern "C" void kernel_launch(void* const* d_in, const int* in_sizes, int n_in,
                              void* d_out, int out_size)
{
    const float* x  = (const float*)d_in[0];
    const float* Wq = (const float*)d_in[1];
    const float* Wk = (const float*)d_in[2];
    const float* Wv = (const float*)d_in[3];
    const float* Wo = (const float*)d_in[4];
    const float* bq = (const float*)d_in[5];
    const float* bk = (const float*)d_in[6];
    const float* bv = (const float*)d_in[7];
    const float* bo = (const float*)d_in[8];
    float* out = (float*)d_out;

    dim3 blk(256);

    qkv_gemm_tc<<<dim3(16, 32, 3), blk>>>(x, Wq, Wk, Wv, bq, bk, bv);

    cudaFuncSetAttribute(attn_tc, cudaFuncAttributeMaxDynamicSharedMemorySize,
                         ATT_SMEM_BYTES);
    attn_tc<<<dim3(32, 32), blk, ATT_SMEM_BYTES>>>();

    out_gemm_tc<<<dim3(16, 32), blk>>>(Wo, bo, out);
}

// round 4
// speedup vs baseline: 5.3560x; 5.3560x over previous
#include <cuda_runtime.h>
#include <math.h>

#define BATCH   2
#define SEQ     2048
#define DMODEL  2048
#define NHEADS  16
#define DHEAD   128

// Scratch (allocation-free: __device__ globals)
__device__ float g_Q[BATCH*NHEADS*SEQ*DHEAD];   // [B][H][S][Dh]
__device__ float g_K[BATCH*NHEADS*SEQ*DHEAD];
__device__ float g_V[BATCH*NHEADS*SEQ*DHEAD];
__device__ float g_Z[BATCH*SEQ*NHEADS*DHEAD];   // [B][S][H][Dh], tf32-rounded values
__device__ float g_Xc [BATCH*SEQ*DMODEL];       // tf32-rounded copies
__device__ float g_Wqc[NHEADS*DMODEL*DHEAD];
__device__ float g_Wkc[NHEADS*DMODEL*DHEAD];
__device__ float g_Wvc[NHEADS*DMODEL*DHEAD];
__device__ float g_WOc[NHEADS*DHEAD*DMODEL];

// ---------------------------------------------------------------------------
// helpers
// ---------------------------------------------------------------------------
__device__ __forceinline__ unsigned f2tf32(float x) {
    unsigned y;
    asm("cvt.rna.tf32.f32 %0, %1;" : "=r"(y) : "f"(x));
    return y;
}
__device__ __forceinline__ float f2tf32f(float x) {
    return __uint_as_float(f2tf32(x));
}

__device__ __forceinline__ void mma_tf32(float* c, const unsigned* a, const unsigned* b) {
    asm volatile(
        "mma.sync.aligned.m16n8k8.row.col.f32.tf32.tf32.f32 "
        "{%0,%1,%2,%3}, {%4,%5,%6,%7}, {%8,%9}, {%0,%1,%2,%3};\n"
        : "+f"(c[0]), "+f"(c[1]), "+f"(c[2]), "+f"(c[3])
        : "r"(a[0]), "r"(a[1]), "r"(a[2]), "r"(a[3]), "r"(b[0]), "r"(b[1]));
}

__device__ __forceinline__ void cp_async16(void* smem_dst, const void* gsrc) {
    unsigned saddr = (unsigned)__cvta_generic_to_shared(smem_dst);
    asm volatile("cp.async.ca.shared.global [%0], [%1], 16;\n" :: "r"(saddr), "l"(gsrc));
}
#define CP_COMMIT() asm volatile("cp.async.commit_group;\n" ::: "memory")
#define CP_WAIT1()  asm volatile("cp.async.wait_group 1;\n" ::: "memory")

// ---------------------------------------------------------------------------
// Pre-pass: round fp32 -> tf32 values (elementwise, float4)
// ---------------------------------------------------------------------------
__global__ void cvt_tf32_kernel(const float4* __restrict__ in, float4* __restrict__ out, int n4)
{
    int i = blockIdx.x * blockDim.x + threadIdx.x;
    if (i < n4) {
        float4 v = in[i];
        float4 r;
        r.x = f2tf32f(v.x); r.y = f2tf32f(v.y);
        r.z = f2tf32f(v.z); r.w = f2tf32f(v.w);
        out[i] = r;
    }
}

// ---------------------------------------------------------------------------
// Shared GEMM mainloop pieces.  Block tile 128x128, k-slab 32, 2-stage cp.async.
// Stage layout: A [128][36] words, then B [32][136] words.
// ---------------------------------------------------------------------------
#define GA_STRIDE 36
#define GB_STRIDE 136
#define GSTAGE_WORDS (128*GA_STRIDE + 32*GB_STRIDE)   // 8960
#define GEMM_SMEM_BYTES (2 * GSTAGE_WORDS * 4)        // 71680

// issue one k-slab's cp.asyncs. Aw: lda for A source, Bw: ldb for B source.
__device__ __forceinline__ void gemm_issue(
    float* stage, const float* __restrict__ Asrc, const float* __restrict__ Bsrc,
    int tid, size_t lda, size_t ldb)
{
    float* As = stage;
    float* Bs = stage + 128 * GA_STRIDE;
    #pragma unroll
    for (int i = 0; i < 4; i++) {
        int c = tid + i * 256;
        int row = c >> 3, col = (c & 7) * 4;
        cp_async16(As + row * GA_STRIDE + col, Asrc + (size_t)row * lda + col);
    }
    #pragma unroll
    for (int i = 0; i < 4; i++) {
        int c = tid + i * 256;
        int row = c >> 5, col = (c & 31) * 4;
        cp_async16(Bs + row * GB_STRIDE + col, Bsrc + (size_t)row * ldb + col);
    }
}

__device__ __forceinline__ void gemm_compute(
    const float* stage, float c[4][4][4], int warpM, int warpN, int lq, int lr)
{
    const unsigned* As = (const unsigned*)stage;
    const unsigned* Bs = (const unsigned*)(stage + 128 * GA_STRIDE);
    #pragma unroll
    for (int kk = 0; kk < 32; kk += 8) {
        unsigned a[4][4], b[4][2];
        const int kc = kk + lr;
        #pragma unroll
        for (int mi = 0; mi < 4; mi++) {
            int r = warpM * 64 + mi * 16 + lq;
            a[mi][0] = As[r * GA_STRIDE + kc];
            a[mi][1] = As[(r + 8) * GA_STRIDE + kc];
            a[mi][2] = As[r * GA_STRIDE + kc + 4];
            a[mi][3] = As[(r + 8) * GA_STRIDE + kc + 4];
        }
        #pragma unroll
        for (int ni = 0; ni < 4; ni++) {
            int nb = warpN * 32 + ni * 8 + lq;
            b[ni][0] = Bs[kc * GB_STRIDE + nb];
            b[ni][1] = Bs[(kc + 4) * GB_STRIDE + nb];
        }
        #pragma unroll
        for (int mi = 0; mi < 4; mi++)
            #pragma unroll
            for (int ni = 0; ni < 4; ni++)
                mma_tf32(c[mi][ni], a[mi], b[ni]);
    }
}

// ---------------------------------------------------------------------------
// Phase 1: QKV projection. grid = (16 heads, 32 m-tiles, 3 {Q,K,V})
// ---------------------------------------------------------------------------
__global__ __launch_bounds__(256) void qkv_gemm_tc(
    const float* __restrict__ bq, const float* __restrict__ bk, const float* __restrict__ bv)
{
    extern __shared__ __align__(16) float smp[];

    const float* W; const float* bias; float* out;
    if (blockIdx.z == 0)      { W = g_Wqc; bias = bq; out = g_Q; }
    else if (blockIdx.z == 1) { W = g_Wkc; bias = bk; out = g_K; }
    else                      { W = g_Wvc; bias = bv; out = g_V; }

    const int h   = blockIdx.x;
    const int m0  = blockIdx.y * 128;
    const int tid = threadIdx.x;
    const int warp = tid >> 5, lane = tid & 31;
    const int warpM = warp >> 2, warpN = warp & 3;
    const int lq = lane >> 2, lr = lane & 3;
    const float* Wh = W + (size_t)h * DMODEL * DHEAD;
    const float* Xb = g_Xc + (size_t)m0 * DMODEL;

    float c[4][4][4];
    #pragma unroll
    for (int mi = 0; mi < 4; mi++)
        #pragma unroll
        for (int ni = 0; ni < 4; ni++)
            #pragma unroll
            for (int j = 0; j < 4; j++) c[mi][ni][j] = 0.f;

    gemm_issue(smp, Xb, Wh, tid, DMODEL, DHEAD);                    CP_COMMIT();
    gemm_issue(smp + GSTAGE_WORDS, Xb + 32, Wh + 32 * DHEAD, tid, DMODEL, DHEAD); CP_COMMIT();

    for (int k0 = 0; k0 < DMODEL; k0 += 32) {
        float* cur = smp + ((k0 >> 5) & 1) * GSTAGE_WORDS;
        CP_WAIT1();
        __syncthreads();
        gemm_compute(cur, c, warpM, warpN, lq, lr);
        __syncthreads();
        if (k0 + 64 < DMODEL)
            gemm_issue(cur, Xb + k0 + 64, Wh + (size_t)(k0 + 64) * DHEAD, tid, DMODEL, DHEAD);
        CP_COMMIT();   // unconditional: keeps pending-group count = 2 at each wait
    }

    #pragma unroll
    for (int mi = 0; mi < 4; mi++) {
        #pragma unroll
        for (int half = 0; half < 2; half++) {
            int m = m0 + warpM * 64 + mi * 16 + lq + half * 8;
            int b_ = m >> 11, s = m & 2047;
            float* orow = out + (((size_t)(b_ * NHEADS + h)) * SEQ + s) * DHEAD;
            #pragma unroll
            for (int ni = 0; ni < 4; ni++) {
                int n = warpN * 32 + ni * 8 + 2 * lr;
                float2 r;
                r.x = c[mi][ni][half * 2 + 0] + bias[h * DHEAD + n];
                r.y = c[mi][ni][half * 2 + 1] + bias[h * DHEAD + n + 1];
                *(float2*)(orow + n) = r;
            }
        }
    }
}

// ---------------------------------------------------------------------------
// Phase 2: causal flash attention (R2 code; epilogue writes tf32-rounded Z).
// grid = (32 q-tiles, B*H), 8 warps: warpR{0..3} x warpC{0,1}.
// ---------------------------------------------------------------------------
#define QP 132
#define KP 132
#define VP 136
#define PP 68
#define AOFF_KV (64*QP)
#define AOFF_P  (AOFF_KV + 64*VP)
#define AOFF_MX (AOFF_P + 64*PP)
#define AOFF_SM (AOFF_MX + 128)
#define ATT_SMEM_BYTES ((AOFF_SM + 128) * 4)   // 87040

__global__ __launch_bounds__(256, 2) void attn_tc()
{
    extern __shared__ unsigned smu[];
    unsigned* Qs  = smu;             // [64][QP] transposed-ish staging (row=q, col=dh)
    unsigned* KVs = smu + AOFF_KV;   // K: [64][KP] row=key / V: [64][VP] row=key
    unsigned* Ps  = smu + AOFF_P;    // [64][PP]
    float* smax = (float*)(smu + AOFF_MX);   // [2][64]
    float* ssum = (float*)(smu + AOFF_SM);   // [2][64]

    const int tid = threadIdx.x;
    const int warp = tid >> 5, lane = tid & 31;
    const int warpR = warp >> 1, warpC = warp & 1;
    const int lq = lane >> 2, lr = lane & 3;
    const int bh = blockIdx.y;
    const int b  = bh >> 4, h = bh & 15;
    const int q0 = blockIdx.x * 64;
    const int r_loc = warpR * 16 + lq;

    const float* Qg = g_Q + (size_t)(b * NHEADS + h) * SEQ * DHEAD;
    const float* Kg = g_K + (size_t)(b * NHEADS + h) * SEQ * DHEAD;
    const float* Vg = g_V + (size_t)(b * NHEADS + h) * SEQ * DHEAD;

    const float scale = 0.08838834764831845f;  // 1/sqrt(128), folded into Q

    #pragma unroll
    for (int i = 0; i < 8; i++) {
        int idx = tid + i * 256;
        int row = idx >> 5, col = (idx & 31) * 4;
        float4 v = *(const float4*)(Qg + (size_t)(q0 + row) * DHEAD + col);
        Qs[row * QP + col + 0] = f2tf32(v.x * scale);
        Qs[row * QP + col + 1] = f2tf32(v.y * scale);
        Qs[row * QP + col + 2] = f2tf32(v.z * scale);
        Qs[row * QP + col + 3] = f2tf32(v.w * scale);
    }

    float o[8][4];
    #pragma unroll
    for (int ni = 0; ni < 8; ni++)
        #pragma unroll
        for (int j = 0; j < 4; j++) o[ni][j] = 0.f;
    float m0v = -INFINITY, m1v = -INFINITY, l0 = 0.f, l1 = 0.f;

    const int ntiles = blockIdx.x + 1;   // causal tile skipping

    for (int kt = 0; kt < ntiles; kt++) {
        const int k0t = kt * 64;
        __syncthreads();
        #pragma unroll
        for (int i = 0; i < 8; i++) {
            int idx = tid + i * 256;
            int row = idx >> 5, col = (idx & 31) * 4;
            float4 v = *(const float4*)(Kg + (size_t)(k0t + row) * DHEAD + col);
            KVs[row * KP + col + 0] = f2tf32(v.x);
            KVs[row * KP + col + 1] = f2tf32(v.y);
            KVs[row * KP + col + 2] = f2tf32(v.z);
            KVs[row * KP + col + 3] = f2tf32(v.w);
        }
        __syncthreads();

        // S = Q K^T : warp 16x32, k=128
        float s[4][4];
        #pragma unroll
        for (int ni = 0; ni < 4; ni++)
            #pragma unroll
            for (int j = 0; j < 4; j++) s[ni][j] = 0.f;

        #pragma unroll
        for (int kk = 0; kk < 128; kk += 8) {
            unsigned aq[4], bb[2];
            const int kc = kk + lr;
            aq[0] = Qs[r_loc * QP + kc];       aq[1] = Qs[(r_loc + 8) * QP + kc];
            aq[2] = Qs[r_loc * QP + kc + 4];   aq[3] = Qs[(r_loc + 8) * QP + kc + 4];
            #pragma unroll
            for (int ni = 0; ni < 4; ni++) {
                int nb = warpC * 32 + ni * 8 + lq;
                bb[0] = KVs[nb * KP + kc];
                bb[1] = KVs[nb * KP + kc + 4];
                mma_tf32(s[ni], aq, bb);
            }
        }

        const int r0g = q0 + r_loc, r1g = r0g + 8;
        float mx0 = -1e30f, mx1 = -1e30f;
        #pragma unroll
        for (int ni = 0; ni < 4; ni++) {
            int cb = k0t + warpC * 32 + ni * 8 + 2 * lr;
            if (cb     > r0g) s[ni][0] = -1e30f;
            if (cb + 1 > r0g) s[ni][1] = -1e30f;
            if (cb     > r1g) s[ni][2] = -1e30f;
            if (cb + 1 > r1g) s[ni][3] = -1e30f;
            mx0 = fmaxf(mx0, fmaxf(s[ni][0], s[ni][1]));
            mx1 = fmaxf(mx1, fmaxf(s[ni][2], s[ni][3]));
        }
        mx0 = fmaxf(mx0, __shfl_xor_sync(0xffffffffu, mx0, 1));
        mx0 = fmaxf(mx0, __shfl_xor_sync(0xffffffffu, mx0, 2));
        mx1 = fmaxf(mx1, __shfl_xor_sync(0xffffffffu, mx1, 1));
        mx1 = fmaxf(mx1, __shfl_xor_sync(0xffffffffu, mx1, 2));
        if (lr == 0) {
            smax[warpC * 64 + r_loc]     = mx0;
            smax[warpC * 64 + r_loc + 8] = mx1;
        }
        __syncthreads();
        mx0 = fmaxf(mx0, smax[(warpC ^ 1) * 64 + r_loc]);
        mx1 = fmaxf(mx1, smax[(warpC ^ 1) * 64 + r_loc + 8]);

        float mn0 = fmaxf(m0v, mx0), mn1 = fmaxf(m1v, mx1);
        float ef0 = __expf(m0v - mn0), ef1 = __expf(m1v - mn1);
        m0v = mn0; m1v = mn1;

        float sum0 = 0.f, sum1 = 0.f;
        #pragma unroll
        for (int ni = 0; ni < 4; ni++) {
            float p0 = __expf(s[ni][0] - mn0);
            float p1 = __expf(s[ni][1] - mn0);
            float p2 = __expf(s[ni][2] - mn1);
            float p3 = __expf(s[ni][3] - mn1);
            sum0 += p0 + p1; sum1 += p2 + p3;
            int kc2 = warpC * 32 + ni * 8 + 2 * lr;
            Ps[r_loc * PP + kc2]           = f2tf32(p0);
            Ps[r_loc * PP + kc2 + 1]       = f2tf32(p1);
            Ps[(r_loc + 8) * PP + kc2]     = f2tf32(p2);
            Ps[(r_loc + 8) * PP + kc2 + 1] = f2tf32(p3);
        }
        sum0 += __shfl_xor_sync(0xffffffffu, sum0, 1);
        sum0 += __shfl_xor_sync(0xffffffffu, sum0, 2);
        sum1 += __shfl_xor_sync(0xffffffffu, sum1, 1);
        sum1 += __shfl_xor_sync(0xffffffffu, sum1, 2);
        if (lr == 0) {
            ssum[warpC * 64 + r_loc]     = sum0;
            ssum[warpC * 64 + r_loc + 8] = sum1;
        }
        #pragma unroll
        for (int ni = 0; ni < 8; ni++) {
            o[ni][0] *= ef0; o[ni][1] *= ef0;
            o[ni][2] *= ef1; o[ni][3] *= ef1;
        }
        #pragma unroll
        for (int i = 0; i < 8; i++) {
            int idx = tid + i * 256;
            int row = idx >> 5, col = (idx & 31) * 4;
            float4 v = *(const float4*)(Vg + (size_t)(k0t + row) * DHEAD + col);
            KVs[row * VP + col + 0] = f2tf32(v.x);
            KVs[row * VP + col + 1] = f2tf32(v.y);
            KVs[row * VP + col + 2] = f2tf32(v.z);
            KVs[row * VP + col + 3] = f2tf32(v.w);
        }
        __syncthreads();

        l0 = l0 * ef0 + sum0 + ssum[(warpC ^ 1) * 64 + r_loc];
        l1 = l1 * ef1 + sum1 + ssum[(warpC ^ 1) * 64 + r_loc + 8];

        #pragma unroll
        for (int kk = 0; kk < 64; kk += 8) {
            unsigned ap[4], bb[2];
            const int kc = kk + lr;
            ap[0] = Ps[r_loc * PP + kc];       ap[1] = Ps[(r_loc + 8) * PP + kc];
            ap[2] = Ps[r_loc * PP + kc + 4];   ap[3] = Ps[(r_loc + 8) * PP + kc + 4];
            #pragma unroll
            for (int ni = 0; ni < 8; ni++) {
                int nb = warpC * 64 + ni * 8 + lq;
                bb[0] = KVs[kc * VP + nb];
                bb[1] = KVs[(kc + 4) * VP + nb];
                mma_tf32(o[ni], ap, bb);
            }
        }
    }

    // normalize + write Z (tf32-rounded so out-proj can cp.async it raw)
    float inv0 = 1.f / l0, inv1 = 1.f / l1;
    const int q_0 = q0 + r_loc;
    #pragma unroll
    for (int ni = 0; ni < 8; ni++) {
        int e = warpC * 64 + ni * 8 + 2 * lr;
        float2 z0; z0.x = f2tf32f(o[ni][0] * inv0); z0.y = f2tf32f(o[ni][1] * inv0);
        float2 z1; z1.x = f2tf32f(o[ni][2] * inv1); z1.y = f2tf32f(o[ni][3] * inv1);
        *(float2*)(g_Z + (((size_t)(b * SEQ + q_0)) * NHEADS + h) * DHEAD + e)     = z0;
        *(float2*)(g_Z + (((size_t)(b * SEQ + q_0 + 8)) * NHEADS + h) * DHEAD + e) = z1;
    }
}

// ---------------------------------------------------------------------------
// Phase 3: output projection. grid = (16 n-tiles, 32 m-tiles)
// ---------------------------------------------------------------------------
__global__ __launch_bounds__(256) void out_gemm_tc(
    const float* __restrict__ bO, float* __restrict__ out)
{
    extern __shared__ __align__(16) float smp[];

    const int n0  = blockIdx.x * 128;
    const int m0  = blockIdx.y * 128;
    const int tid = threadIdx.x;
    const int warp = tid >> 5, lane = tid & 31;
    const int warpM = warp >> 2, warpN = warp & 3;
    const int lq = lane >> 2, lr = lane & 3;

    const float* Asrc = g_Z + (size_t)m0 * DMODEL;
    const float* Bsrc = g_WOc + n0;

    float c[4][4][4];
    #pragma unroll
    for (int mi = 0; mi < 4; mi++)
        #pragma unroll
        for (int ni = 0; ni < 4; ni++)
            #pragma unroll
            for (int j = 0; j < 4; j++) c[mi][ni][j] = 0.f;

    gemm_issue(smp, Asrc, Bsrc, tid, DMODEL, DMODEL);                               CP_COMMIT();
    gemm_issue(smp + GSTAGE_WORDS, Asrc + 32, Bsrc + (size_t)32 * DMODEL, tid, DMODEL, DMODEL); CP_COMMIT();

    for (int k0 = 0; k0 < DMODEL; k0 += 32) {
        float* cur = smp + ((k0 >> 5) & 1) * GSTAGE_WORDS;
        CP_WAIT1();
        __syncthreads();
        gemm_compute(cur, c, warpM, warpN, lq, lr);
        __syncthreads();
        if (k0 + 64 < DMODEL)
            gemm_issue(cur, Asrc + k0 + 64, Bsrc + (size_t)(k0 + 64) * DMODEL, tid, DMODEL, DMODEL);
        CP_COMMIT();
    }

    #pragma unroll
    for (int mi = 0; mi < 4; mi++) {
        #pragma unroll
        for (int half = 0; half < 2; half++) {
            int m = m0 + warpM * 64 + mi * 16 + lq + half * 8;
            float* orow = out + (size_t)m * DMODEL + n0;
            #pragma unroll
            for (int ni = 0; ni < 4; ni++) {
                int n = warpN * 32 + ni * 8 + 2 * lr;
                float2 r;
                r.x = c[mi][ni][half * 2 + 0] + bO[n0 + n];
                r.y = c[mi][ni][half * 2 + 1] + bO[n0 + n + 1];
                *(float2*)(orow + n) = r;
            }
        }
    }
}

// ---------------------------------------------------------------------------
extern "C" void kernel_launch(void* const* d_in, const int* in_sizes, int n_in,
                              void* d_out, int out_size)
{
    const float* x  = (const float*)d_in[0];
    const float* Wq = (const float*)d_in[1];
    const float* Wk = (const float*)d_in[2];
    const float* Wv = (const float*)d_in[3];
    const float* Wo = (const float*)d_in[4];
    const float* bq = (const float*)d_in[5];
    const float* bk = (const float*)d_in[6];
    const float* bv = (const float*)d_in[7];
    const float* bo = (const float*)d_in[8];
    float* out = (float*)d_out;

    // resolve device-global scratch addresses (host side)
    float *pXc, *pWqc, *pWkc, *pWvc, *pWOc;
    cudaGetSymbolAddress((void**)&pXc,  g_Xc);
    cudaGetSymbolAddress((void**)&pWqc, g_Wqc);
    cudaGetSymbolAddress((void**)&pWkc, g_Wkc);
    cudaGetSymbolAddress((void**)&pWvc, g_Wvc);
    cudaGetSymbolAddress((void**)&pWOc, g_WOc);

    const int NX = BATCH*SEQ*DMODEL/4, NW = NHEADS*DMODEL*DHEAD/4;
    cvt_tf32_kernel<<<(NX+255)/256, 256>>>((const float4*)x,  (float4*)pXc,  NX);
    cvt_tf32_kernel<<<(NW+255)/256, 256>>>((const float4*)Wq, (float4*)pWqc, NW);
    cvt_tf32_kernel<<<(NW+255)/256, 256>>>((const float4*)Wk, (float4*)pWkc, NW);
    cvt_tf32_kernel<<<(NW+255)/256, 256>>>((const float4*)Wv, (float4*)pWvc, NW);
    cvt_tf32_kernel<<<(NW+255)/256, 256>>>((const float4*)Wo, (float4*)pWOc, NW);

    dim3 blk(256);

    cudaFuncSetAttribute(qkv_gemm_tc, cudaFuncAttributeMaxDynamicSharedMemorySize, GEMM_SMEM_BYTES);
    qkv_gemm_tc<<<dim3(16, 32, 3), blk, GEMM_SMEM_BYTES>>>(bq, bk, bv);

    cudaFuncSetAttribute(attn_tc, cudaFuncAttributeMaxDynamicSharedMemorySize, ATT_SMEM_BYTES);
    attn_tc<<<dim3(32, 32), blk, ATT_SMEM_BYTES>>>();

    cudaFuncSetAttribute(out_gemm_tc, cudaFuncAttributeMaxDynamicSharedMemorySize, GEMM_SMEM_BYTES);
    out_gemm_tc<<<dim3(16, 32), blk, GEMM_SMEM_BYTES>>>(bo, out);
}

// round 5
// speedup vs baseline: 5.7077x; 1.0657x over previous
#include <cuda_runtime.h>
#include <math.h>

#define BATCH   2
#define SEQ     2048
#define DMODEL  2048
#define NHEADS  16
#define DHEAD   128

// Scratch (allocation-free: __device__ globals)
__device__ float g_Q[BATCH*NHEADS*SEQ*DHEAD];   // [B][H][S][Dh]
__device__ float g_K[BATCH*NHEADS*SEQ*DHEAD];
__device__ float g_V[BATCH*NHEADS*SEQ*DHEAD];
// Fragment-permuted operands (tf32-rounded):
__device__ float g_Xp [BATCH*SEQ*DMODEL];       // A-frag: [m-tile(32)][slab(64)][4096]
__device__ float g_Zp [BATCH*SEQ*NHEADS*DHEAD]; // A-frag: [m-tile(32)][slab(64)][4096]
__device__ float g_Wqp[NHEADS*DMODEL*DHEAD];    // B-frag: [head(16)][slab(64)][4096]
__device__ float g_Wkp[NHEADS*DMODEL*DHEAD];
__device__ float g_Wvp[NHEADS*DMODEL*DHEAD];
__device__ float g_WOp[NHEADS*DHEAD*DMODEL];    // B-frag: [n-tile(16)][slab(64)][4096]

#define SLAB_WORDS 4096
#define MAT_WORDS  (64*SLAB_WORDS)   // one 2048x128 operand panel

// ---------------------------------------------------------------------------
// helpers
// ---------------------------------------------------------------------------
__device__ __forceinline__ unsigned f2tf32(float x) {
    unsigned y;
    asm("cvt.rna.tf32.f32 %0, %1;" : "=r"(y) : "f"(x));
    return y;
}
__device__ __forceinline__ float f2tf32f(float x) { return __uint_as_float(f2tf32(x)); }

__device__ __forceinline__ void mma_tf32(float* c, const unsigned* a, const unsigned* b) {
    asm volatile(
        "mma.sync.aligned.m16n8k8.row.col.f32.tf32.tf32.f32 "
        "{%0,%1,%2,%3}, {%4,%5,%6,%7}, {%8,%9}, {%0,%1,%2,%3};\n"
        : "+f"(c[0]), "+f"(c[1]), "+f"(c[2]), "+f"(c[3])
        : "r"(a[0]), "r"(a[1]), "r"(a[2]), "r"(a[3]), "r"(b[0]), "r"(b[1]));
}

__device__ __forceinline__ void cp_async16(void* smem_dst, const void* gsrc) {
    unsigned saddr = (unsigned)__cvta_generic_to_shared(smem_dst);
    asm volatile("cp.async.ca.shared.global [%0], [%1], 16;\n" :: "r"(saddr), "l"(gsrc));
}
#define CP_COMMIT() asm volatile("cp.async.commit_group;\n" ::: "memory")
#define CP_WAIT1()  asm volatile("cp.async.wait_group 1;\n" ::: "memory")

// A-frag word index within a 128x32 slab (Kq fixed at 4)
__device__ __forceinline__ int afrag(int m, int k) {
    return ((((m >> 4) * 4 + (k >> 3)) * 32 + (m & 7) * 4 + (k & 3)) << 2)
           + (((k & 4) >> 1) | ((m & 8) >> 3));
}

// ---------------------------------------------------------------------------
// Prepass: permute+round A operand (X -> g_Xp).
// One thread per 16B output chunk; chunk = 4 regs of one (lane, mt, kt) cell.
// ---------------------------------------------------------------------------
__global__ __launch_bounds__(256) void permute_A_kernel(
    const float* __restrict__ src, float* __restrict__ dst, int nchunks)
{
    int gid = blockIdx.x * blockDim.x + threadIdx.x;
    if (gid >= nchunks) return;
    int c    = gid & 1023;           // chunk within slab
    int slab = (gid >> 10) & 63;     // k-slab
    int mt_g = gid >> 16;            // 128-row m-tile
    int lane = c & 31, t = c >> 5;
    int kt = t & 3, mt = t >> 2;
    int m = mt_g * 128 + mt * 16 + (lane >> 2);
    int k = slab * 32 + kt * 8 + (lane & 3);
    const float* s = src + (size_t)m * DMODEL + k;
    float4 o;
    o.x = f2tf32f(s[0]);                       // (m,   k)
    o.y = f2tf32f(s[(size_t)8 * DMODEL]);      // (m+8, k)
    o.z = f2tf32f(s[4]);                       // (m,   k+4)
    o.w = f2tf32f(s[(size_t)8 * DMODEL + 4]);  // (m+8, k+4)
    *(float4*)(dst + (size_t)gid * 4) = o;
}

// ---------------------------------------------------------------------------
// Prepass: permute+round B operand. Each "mat" is a 2048 x 128 column panel:
// QKV weights: mat = head, mat_off = h*2048*128, ld = 128.
// WO:          mat = n-tile, mat_off = nt*128,   ld = 2048.
// ---------------------------------------------------------------------------
__global__ __launch_bounds__(256) void permute_B_kernel(
    const float* __restrict__ src, float* __restrict__ dst,
    size_t mat_off_stride, int ld, int nchunks)
{
    int gid = blockIdx.x * blockDim.x + threadIdx.x;
    if (gid >= nchunks) return;
    int c    = gid & 1023;
    int slab = (gid >> 10) & 63;
    int mat  = gid >> 16;
    int pair = c * 2;
    int lane = pair & 31, t = pair >> 5;     // lane even
    int nt8 = t & 15, kt = t >> 4;
    int k = slab * 32 + kt * 8 + (lane & 3);
    int n = nt8 * 8 + (lane >> 2);
    const float* s = src + mat * mat_off_stride + (size_t)k * ld + n;
    float4 o;
    o.x = f2tf32f(s[0]);                 // (k,   n)
    o.y = f2tf32f(s[(size_t)4 * ld]);    // (k+4, n)
    o.z = f2tf32f(s[(size_t)1 * ld]);    // (k+1, n)
    o.w = f2tf32f(s[(size_t)5 * ld]);    // (k+5, n)
    *(float4*)(dst + (size_t)gid * 4) = o;
}

// ---------------------------------------------------------------------------
// GEMM mainloop pieces: block tile 128x128, k-slab 32, 2-stage cp.async.
// Stage: A slab (4096 words) then B slab (4096 words), both fragment-ordered.
// ---------------------------------------------------------------------------
#define GSTAGE_WORDS (2 * SLAB_WORDS)            // 8192
#define GEMM_SMEM_BYTES (2 * GSTAGE_WORDS * 4)   // 65536

__device__ __forceinline__ void gemm_issue_p(
    float* stage, const float* __restrict__ Ablk, const float* __restrict__ Bblk, int tid)
{
    #pragma unroll
    for (int i = 0; i < 4; i++) {
        int c = tid + i * 256;
        cp_async16(stage + c * 4, Ablk + (size_t)c * 4);
        cp_async16(stage + SLAB_WORDS + c * 4, Bblk + (size_t)c * 4);
    }
}

__device__ __forceinline__ void gemm_compute_p(
    const float* stage, float c[4][4][4], int warpM, int warpN, int lane)
{
    const uint4* A4 = (const uint4*)stage;
    const uint2* B2 = (const uint2*)(stage + SLAB_WORDS);
    #pragma unroll
    for (int kt = 0; kt < 4; kt++) {
        uint4 a[4]; uint2 b[4];
        #pragma unroll
        for (int mi = 0; mi < 4; mi++)
            a[mi] = A4[((warpM * 4 + mi) * 4 + kt) * 32 + lane];
        #pragma unroll
        for (int ni = 0; ni < 4; ni++)
            b[ni] = B2[(kt * 16 + warpN * 4 + ni) * 32 + lane];
        #pragma unroll
        for (int mi = 0; mi < 4; mi++)
            #pragma unroll
            for (int ni = 0; ni < 4; ni++)
                mma_tf32(c[mi][ni], (const unsigned*)&a[mi], (const unsigned*)&b[ni]);
    }
}

// ---------------------------------------------------------------------------
// Phase 1: QKV projection. grid = (16 heads, 32 m-tiles, 3 {Q,K,V})
// ---------------------------------------------------------------------------
__global__ __launch_bounds__(256) void qkv_gemm_tc(
    const float* __restrict__ bq, const float* __restrict__ bk, const float* __restrict__ bv)
{
    extern __shared__ __align__(16) float smp[];

    const float* W; const float* bias; float* out;
    if (blockIdx.z == 0)      { W = g_Wqp; bias = bq; out = g_Q; }
    else if (blockIdx.z == 1) { W = g_Wkp; bias = bk; out = g_K; }
    else                      { W = g_Wvp; bias = bv; out = g_V; }

    const int h   = blockIdx.x;
    const int m0  = blockIdx.y * 128;
    const int tid = threadIdx.x;
    const int warp = tid >> 5, lane = tid & 31;
    const int warpM = warp >> 2, warpN = warp & 3;
    const int lq = lane >> 2, lr = lane & 3;
    const float* Ablk0 = g_Xp + (size_t)(m0 >> 7) * MAT_WORDS;
    const float* Bblk0 = W + (size_t)h * MAT_WORDS;

    float c[4][4][4];
    #pragma unroll
    for (int mi = 0; mi < 4; mi++)
        #pragma unroll
        for (int ni = 0; ni < 4; ni++)
            #pragma unroll
            for (int j = 0; j < 4; j++) c[mi][ni][j] = 0.f;

    gemm_issue_p(smp, Ablk0, Bblk0, tid);                                             CP_COMMIT();
    gemm_issue_p(smp + GSTAGE_WORDS, Ablk0 + SLAB_WORDS, Bblk0 + SLAB_WORDS, tid);    CP_COMMIT();

    for (int s = 0; s < 64; s++) {
        float* cur = smp + (s & 1) * GSTAGE_WORDS;
        CP_WAIT1();
        __syncthreads();
        gemm_compute_p(cur, c, warpM, warpN, lane);
        __syncthreads();
        if (s + 2 < 64)
            gemm_issue_p(cur, Ablk0 + (size_t)(s + 2) * SLAB_WORDS,
                              Bblk0 + (size_t)(s + 2) * SLAB_WORDS, tid);
        CP_COMMIT();   // unconditional: pending-group count stays 2 at each wait
    }

    #pragma unroll
    for (int mi = 0; mi < 4; mi++) {
        #pragma unroll
        for (int half = 0; half < 2; half++) {
            int m = m0 + warpM * 64 + mi * 16 + lq + half * 8;
            int b_ = m >> 11, sdx = m & 2047;
            float* orow = out + (((size_t)(b_ * NHEADS + h)) * SEQ + sdx) * DHEAD;
            #pragma unroll
            for (int ni = 0; ni < 4; ni++) {
                int n = warpN * 32 + ni * 8 + 2 * lr;
                float2 r;
                r.x = c[mi][ni][half * 2 + 0] + bias[h * DHEAD + n];
                r.y = c[mi][ni][half * 2 + 1] + bias[h * DHEAD + n + 1];
                *(float2*)(orow + n) = r;
            }
        }
    }
}

// ---------------------------------------------------------------------------
// Phase 2: causal flash attention (R4 body; epilogue writes g_Zp A-frag layout)
// ---------------------------------------------------------------------------
#define QP 132
#define KP 132
#define VP 136
#define PP 68
#define AOFF_KV (64*QP)
#define AOFF_P  (AOFF_KV + 64*VP)
#define AOFF_MX (AOFF_P + 64*PP)
#define AOFF_SM (AOFF_MX + 128)
#define ATT_SMEM_BYTES ((AOFF_SM + 128) * 4)   // 87040

__global__ __launch_bounds__(256, 2) void attn_tc()
{
    extern __shared__ unsigned smu[];
    unsigned* Qs  = smu;
    unsigned* KVs = smu + AOFF_KV;
    unsigned* Ps  = smu + AOFF_P;
    float* smax = (float*)(smu + AOFF_MX);
    float* ssum = (float*)(smu + AOFF_SM);

    const int tid = threadIdx.x;
    const int warp = tid >> 5, lane = tid & 31;
    const int warpR = warp >> 1, warpC = warp & 1;
    const int lq = lane >> 2, lr = lane & 3;
    const int bh = blockIdx.y;
    const int b  = bh >> 4, h = bh & 15;
    const int q0 = blockIdx.x * 64;
    const int r_loc = warpR * 16 + lq;

    const float* Qg = g_Q + (size_t)(b * NHEADS + h) * SEQ * DHEAD;
    const float* Kg = g_K + (size_t)(b * NHEADS + h) * SEQ * DHEAD;
    const float* Vg = g_V + (size_t)(b * NHEADS + h) * SEQ * DHEAD;

    const float scale = 0.08838834764831845f;

    #pragma unroll
    for (int i = 0; i < 8; i++) {
        int idx = tid + i * 256;
        int row = idx >> 5, col = (idx & 31) * 4;
        float4 v = *(const float4*)(Qg + (size_t)(q0 + row) * DHEAD + col);
        Qs[row * QP + col + 0] = f2tf32(v.x * scale);
        Qs[row * QP + col + 1] = f2tf32(v.y * scale);
        Qs[row * QP + col + 2] = f2tf32(v.z * scale);
        Qs[row * QP + col + 3] = f2tf32(v.w * scale);
    }

    float o[8][4];
    #pragma unroll
    for (int ni = 0; ni < 8; ni++)
        #pragma unroll
        for (int j = 0; j < 4; j++) o[ni][j] = 0.f;
    float m0v = -INFINITY, m1v = -INFINITY, l0 = 0.f, l1 = 0.f;

    const int ntiles = blockIdx.x + 1;

    for (int kt = 0; kt < ntiles; kt++) {
        const int k0t = kt * 64;
        __syncthreads();
        #pragma unroll
        for (int i = 0; i < 8; i++) {
            int idx = tid + i * 256;
            int row = idx >> 5, col = (idx & 31) * 4;
            float4 v = *(const float4*)(Kg + (size_t)(k0t + row) * DHEAD + col);
            KVs[row * KP + col + 0] = f2tf32(v.x);
            KVs[row * KP + col + 1] = f2tf32(v.y);
            KVs[row * KP + col + 2] = f2tf32(v.z);
            KVs[row * KP + col + 3] = f2tf32(v.w);
        }
        __syncthreads();

        float s[4][4];
        #pragma unroll
        for (int ni = 0; ni < 4; ni++)
            #pragma unroll
            for (int j = 0; j < 4; j++) s[ni][j] = 0.f;

        #pragma unroll
        for (int kk = 0; kk < 128; kk += 8) {
            unsigned aq[4], bb[2];
            const int kc = kk + lr;
            aq[0] = Qs[r_loc * QP + kc];       aq[1] = Qs[(r_loc + 8) * QP + kc];
            aq[2] = Qs[r_loc * QP + kc + 4];   aq[3] = Qs[(r_loc + 8) * QP + kc + 4];
            #pragma unroll
            for (int ni = 0; ni < 4; ni++) {
                int nb = warpC * 32 + ni * 8 + lq;
                bb[0] = KVs[nb * KP + kc];
                bb[1] = KVs[nb * KP + kc + 4];
                mma_tf32(s[ni], aq, bb);
            }
        }

        const int r0g = q0 + r_loc, r1g = r0g + 8;
        float mx0 = -1e30f, mx1 = -1e30f;
        #pragma unroll
        for (int ni = 0; ni < 4; ni++) {
            int cb = k0t + warpC * 32 + ni * 8 + 2 * lr;
            if (cb     > r0g) s[ni][0] = -1e30f;
            if (cb + 1 > r0g) s[ni][1] = -1e30f;
            if (cb     > r1g) s[ni][2] = -1e30f;
            if (cb + 1 > r1g) s[ni][3] = -1e30f;
            mx0 = fmaxf(mx0, fmaxf(s[ni][0], s[ni][1]));
            mx1 = fmaxf(mx1, fmaxf(s[ni][2], s[ni][3]));
        }
        mx0 = fmaxf(mx0, __shfl_xor_sync(0xffffffffu, mx0, 1));
        mx0 = fmaxf(mx0, __shfl_xor_sync(0xffffffffu, mx0, 2));
        mx1 = fmaxf(mx1, __shfl_xor_sync(0xffffffffu, mx1, 1));
        mx1 = fmaxf(mx1, __shfl_xor_sync(0xffffffffu, mx1, 2));
        if (lr == 0) {
            smax[warpC * 64 + r_loc]     = mx0;
            smax[warpC * 64 + r_loc + 8] = mx1;
        }
        __syncthreads();
        mx0 = fmaxf(mx0, smax[(warpC ^ 1) * 64 + r_loc]);
        mx1 = fmaxf(mx1, smax[(warpC ^ 1) * 64 + r_loc + 8]);

        float mn0 = fmaxf(m0v, mx0), mn1 = fmaxf(m1v, mx1);
        float ef0 = __expf(m0v - mn0), ef1 = __expf(m1v - mn1);
        m0v = mn0; m1v = mn1;

        float sum0 = 0.f, sum1 = 0.f;
        #pragma unroll
        for (int ni = 0; ni < 4; ni++) {
            float p0 = __expf(s[ni][0] - mn0);
            float p1 = __expf(s[ni][1] - mn0);
            float p2 = __expf(s[ni][2] - mn1);
            float p3 = __expf(s[ni][3] - mn1);
            sum0 += p0 + p1; sum1 += p2 + p3;
            int kc2 = warpC * 32 + ni * 8 + 2 * lr;
            Ps[r_loc * PP + kc2]           = f2tf32(p0);
            Ps[r_loc * PP + kc2 + 1]       = f2tf32(p1);
            Ps[(r_loc + 8) * PP + kc2]     = f2tf32(p2);
            Ps[(r_loc + 8) * PP + kc2 + 1] = f2tf32(p3);
        }
        sum0 += __shfl_xor_sync(0xffffffffu, sum0, 1);
        sum0 += __shfl_xor_sync(0xffffffffu, sum0, 2);
        sum1 += __shfl_xor_sync(0xffffffffu, sum1, 1);
        sum1 += __shfl_xor_sync(0xffffffffu, sum1, 2);
        if (lr == 0) {
            ssum[warpC * 64 + r_loc]     = sum0;
            ssum[warpC * 64 + r_loc + 8] = sum1;
        }
        #pragma unroll
        for (int ni = 0; ni < 8; ni++) {
            o[ni][0] *= ef0; o[ni][1] *= ef0;
            o[ni][2] *= ef1; o[ni][3] *= ef1;
        }
        #pragma unroll
        for (int i = 0; i < 8; i++) {
            int idx = tid + i * 256;
            int row = idx >> 5, col = (idx & 31) * 4;
            float4 v = *(const float4*)(Vg + (size_t)(k0t + row) * DHEAD + col);
            KVs[row * VP + col + 0] = f2tf32(v.x);
            KVs[row * VP + col + 1] = f2tf32(v.y);
            KVs[row * VP + col + 2] = f2tf32(v.z);
            KVs[row * VP + col + 3] = f2tf32(v.w);
        }
        __syncthreads();

        l0 = l0 * ef0 + sum0 + ssum[(warpC ^ 1) * 64 + r_loc];
        l1 = l1 * ef1 + sum1 + ssum[(warpC ^ 1) * 64 + r_loc + 8];

        #pragma unroll
        for (int kk = 0; kk < 64; kk += 8) {
            unsigned ap[4], bb[2];
            const int kc = kk + lr;
            ap[0] = Ps[r_loc * PP + kc];       ap[1] = Ps[(r_loc + 8) * PP + kc];
            ap[2] = Ps[r_loc * PP + kc + 4];   ap[3] = Ps[(r_loc + 8) * PP + kc + 4];
            #pragma unroll
            for (int ni = 0; ni < 8; ni++) {
                int nb = warpC * 64 + ni * 8 + lq;
                bb[0] = KVs[kc * VP + nb];
                bb[1] = KVs[(kc + 4) * VP + nb];
                mma_tf32(o[ni], ap, bb);
            }
        }
    }

    // normalize + scatter-write Z into A-frag permuted layout (tf32-rounded)
    float inv0 = 1.f / l0, inv1 = 1.f / l1;
    const int mglob0 = b * SEQ + q0;          // 64-aligned
    float* Zt = g_Zp + (size_t)(mglob0 >> 7) * MAT_WORDS;
    const int mrow = (mglob0 & 127) + r_loc;  // row within 128-row m-tile
    #pragma unroll
    for (int ni = 0; ni < 8; ni++) {
        int e = warpC * 64 + ni * 8 + 2 * lr;
        int kg = h * DHEAD + e;
        float* Zs = Zt + (size_t)(kg >> 5) * SLAB_WORDS;
        int kk = kg & 31;
        Zs[afrag(mrow,     kk)]     = f2tf32f(o[ni][0] * inv0);
        Zs[afrag(mrow,     kk + 1)] = f2tf32f(o[ni][1] * inv0);
        Zs[afrag(mrow + 8, kk)]     = f2tf32f(o[ni][2] * inv1);
        Zs[afrag(mrow + 8, kk + 1)] = f2tf32f(o[ni][3] * inv1);
    }
}

// ---------------------------------------------------------------------------
// Phase 3: output projection. grid = (16 n-tiles, 32 m-tiles)
// ---------------------------------------------------------------------------
__global__ __launch_bounds__(256) void out_gemm_tc(
    const float* __restrict__ bO, float* __restrict__ out)
{
    extern __shared__ __align__(16) float smp[];

    const int n0  = blockIdx.x * 128;
    const int m0  = blockIdx.y * 128;
    const int tid = threadIdx.x;
    const int warp = tid >> 5, lane = tid & 31;
    const int warpM = warp >> 2, warpN = warp & 3;
    const int lq = lane >> 2, lr = lane & 3;

    const float* Ablk0 = g_Zp + (size_t)(m0 >> 7) * MAT_WORDS;
    const float* Bblk0 = g_WOp + (size_t)(n0 >> 7) * MAT_WORDS;

    float c[4][4][4];
    #pragma unroll
    for (int mi = 0; mi < 4; mi++)
        #pragma unroll
        for (int ni = 0; ni < 4; ni++)
            #pragma unroll
            for (int j = 0; j < 4; j++) c[mi][ni][j] = 0.f;

    gemm_issue_p(smp, Ablk0, Bblk0, tid);                                           CP_COMMIT();
    gemm_issue_p(smp + GSTAGE_WORDS, Ablk0 + SLAB_WORDS, Bblk0 + SLAB_WORDS, tid);  CP_COMMIT();

    for (int s = 0; s < 64; s++) {
        float* cur = smp + (s & 1) * GSTAGE_WORDS;
        CP_WAIT1();
        __syncthreads();
        gemm_compute_p(cur, c, warpM, warpN, lane);
        __syncthreads();
        if (s + 2 < 64)
            gemm_issue_p(cur, Ablk0 + (size_t)(s + 2) * SLAB_WORDS,
                              Bblk0 + (size_t)(s + 2) * SLAB_WORDS, tid);
        CP_COMMIT();
    }

    #pragma unroll
    for (int mi = 0; mi < 4; mi++) {
        #pragma unroll
        for (int half = 0; half < 2; half++) {
            int m = m0 + warpM * 64 + mi * 16 + lq + half * 8;
            float* orow = out + (size_t)m * DMODEL + n0;
            #pragma unroll
            for (int ni = 0; ni < 4; ni++) {
                int n = warpN * 32 + ni * 8 + 2 * lr;
                float2 r;
                r.x = c[mi][ni][half * 2 + 0] + bO[n0 + n];
                r.y = c[mi][ni][half * 2 + 1] + bO[n0 + n + 1];
                *(float2*)(orow + n) = r;
            }
        }
    }
}

// ---------------------------------------------------------------------------
extern "C" void kernel_launch(void* const* d_in, const int* in_sizes, int n_in,
                              void* d_out, int out_size)
{
    const float* x  = (const float*)d_in[0];
    const float* Wq = (const float*)d_in[1];
    const float* Wk = (const float*)d_in[2];
    const float* Wv = (const float*)d_in[3];
    const float* Wo = (const float*)d_in[4];
    const float* bq = (const float*)d_in[5];
    const float* bk = (const float*)d_in[6];
    const float* bv = (const float*)d_in[7];
    const float* bo = (const float*)d_in[8];
    float* out = (float*)d_out;

    float *pXp, *pWqp, *pWkp, *pWvp, *pWOp;
    cudaGetSymbolAddress((void**)&pXp,  g_Xp);
    cudaGetSymbolAddress((void**)&pWqp, g_Wqp);
    cudaGetSymbolAddress((void**)&pWkp, g_Wkp);
    cudaGetSymbolAddress((void**)&pWvp, g_Wvp);
    cudaGetSymbolAddress((void**)&pWOp, g_WOp);

    const int NXC = BATCH*SEQ*DMODEL/4;            // A chunks
    const int NWC = NHEADS*DMODEL*DHEAD/4;         // B chunks per weight
    permute_A_kernel<<<(NXC+255)/256, 256>>>(x, pXp, NXC);
    permute_B_kernel<<<(NWC+255)/256, 256>>>(Wq, pWqp, (size_t)DMODEL*DHEAD, DHEAD, NWC);
    permute_B_kernel<<<(NWC+255)/256, 256>>>(Wk, pWkp, (size_t)DMODEL*DHEAD, DHEAD, NWC);
    permute_B_kernel<<<(NWC+255)/256, 256>>>(Wv, pWvp, (size_t)DMODEL*DHEAD, DHEAD, NWC);
    permute_B_kernel<<<(NWC+255)/256, 256>>>(Wo, pWOp, (size_t)128, DMODEL, NWC);

    dim3 blk(256);

    cudaFuncSetAttribute(qkv_gemm_tc, cudaFuncAttributeMaxDynamicSharedMemorySize, GEMM_SMEM_BYTES);
    qkv_gemm_tc<<<dim3(16, 32, 3), blk, GEMM_SMEM_BYTES>>>(bq, bk, bv);

    cudaFuncSetAttribute(attn_tc, cudaFuncAttributeMaxDynamicSharedMemorySize, ATT_SMEM_BYTES);
    attn_tc<<<dim3(32, 32), blk, ATT_SMEM_BYTES>>>();

    cudaFuncSetAttribute(out_gemm_tc, cudaFuncAttributeMaxDynamicSharedMemorySize, GEMM_SMEM_BYTES);
    out_gemm_tc<<<dim3(16, 32), blk, GEMM_SMEM_BYTES>>>(bo, out);
}

// round 6
// speedup vs baseline: 5.9103x; 1.0355x over previous
#include <cuda_runtime.h>
#include <math.h>

#define BATCH   2
#define SEQ     2048
#define DMODEL  2048
#define NHEADS  16
#define DHEAD   128
#define SCALE   0.08838834764831845f   // 1/sqrt(128)

// Scratch (allocation-free: __device__ globals)
__device__ float g_Q[BATCH*NHEADS*SEQ*DHEAD];   // [B][H][S][Dh] tf32-rounded, Q pre-scaled
__device__ float g_K[BATCH*NHEADS*SEQ*DHEAD];
__device__ float g_V[BATCH*NHEADS*SEQ*DHEAD];
// Fragment-permuted operands (tf32-rounded):
__device__ float g_Xp [BATCH*SEQ*DMODEL];       // A-frag: [m-tile(32)][slab(64)][4096]
__device__ float g_Zp [BATCH*SEQ*NHEADS*DHEAD]; // A-frag
__device__ float g_Wqp[NHEADS*DMODEL*DHEAD];    // B-frag (pre-scaled by 1/sqrt(128))
__device__ float g_Wkp[NHEADS*DMODEL*DHEAD];
__device__ float g_Wvp[NHEADS*DMODEL*DHEAD];
__device__ float g_WOp[NHEADS*DHEAD*DMODEL];

#define SLAB_WORDS 4096
#define MAT_WORDS  (64*SLAB_WORDS)

// ---------------------------------------------------------------------------
// helpers
// ---------------------------------------------------------------------------
__device__ __forceinline__ unsigned f2tf32(float x) {
    unsigned y;
    asm("cvt.rna.tf32.f32 %0, %1;" : "=r"(y) : "f"(x));
    return y;
}
__device__ __forceinline__ float f2tf32f(float x) { return __uint_as_float(f2tf32(x)); }

__device__ __forceinline__ void mma_tf32(float* c, const unsigned* a, const unsigned* b) {
    asm volatile(
        "mma.sync.aligned.m16n8k8.row.col.f32.tf32.tf32.f32 "
        "{%0,%1,%2,%3}, {%4,%5,%6,%7}, {%8,%9}, {%0,%1,%2,%3};\n"
        : "+f"(c[0]), "+f"(c[1]), "+f"(c[2]), "+f"(c[3])
        : "r"(a[0]), "r"(a[1]), "r"(a[2]), "r"(a[3]), "r"(b[0]), "r"(b[1]));
}

__device__ __forceinline__ void cp_async16(void* smem_dst, const void* gsrc) {
    unsigned saddr = (unsigned)__cvta_generic_to_shared(smem_dst);
    asm volatile("cp.async.ca.shared.global [%0], [%1], 16;\n" :: "r"(saddr), "l"(gsrc));
}
#define CP_COMMIT() asm volatile("cp.async.commit_group;\n" ::: "memory")
#define CP_WAIT0()  asm volatile("cp.async.wait_group 0;\n" ::: "memory")
#define CP_WAIT2()  asm volatile("cp.async.wait_group 2;\n" ::: "memory")

// A-frag word index within a 128x32 slab
__device__ __forceinline__ int afrag(int m, int k) {
    return ((((m >> 4) * 4 + (k >> 3)) * 32 + (m & 7) * 4 + (k & 3)) << 2)
           + (((k & 4) >> 1) | ((m & 8) >> 3));
}

// ---------------------------------------------------------------------------
// Prepass: permute+round A operand (X -> g_Xp)
// ---------------------------------------------------------------------------
__global__ __launch_bounds__(256) void permute_A_kernel(
    const float* __restrict__ src, float* __restrict__ dst, int nchunks)
{
    int gid = blockIdx.x * blockDim.x + threadIdx.x;
    if (gid >= nchunks) return;
    int c    = gid & 1023;
    int slab = (gid >> 10) & 63;
    int mt_g = gid >> 16;
    int lane = c & 31, t = c >> 5;
    int kt = t & 3, mt = t >> 2;
    int m = mt_g * 128 + mt * 16 + (lane >> 2);
    int k = slab * 32 + kt * 8 + (lane & 3);
    const float* s = src + (size_t)m * DMODEL + k;
    float4 o;
    o.x = f2tf32f(s[0]);
    o.y = f2tf32f(s[(size_t)8 * DMODEL]);
    o.z = f2tf32f(s[4]);
    o.w = f2tf32f(s[(size_t)8 * DMODEL + 4]);
    *(float4*)(dst + (size_t)gid * 4) = o;
}

// ---------------------------------------------------------------------------
// Prepass: permute+round B operand (optionally scaled pre-rounding).
// ---------------------------------------------------------------------------
__global__ __launch_bounds__(256) void permute_B_kernel(
    const float* __restrict__ src, float* __restrict__ dst,
    size_t mat_off_stride, int ld, int nchunks, float scl)
{
    int gid = blockIdx.x * blockDim.x + threadIdx.x;
    if (gid >= nchunks) return;
    int c    = gid & 1023;
    int slab = (gid >> 10) & 63;
    int mat  = gid >> 16;
    int pair = c * 2;
    int lane = pair & 31, t = pair >> 5;
    int nt8 = t & 15, kt = t >> 4;
    int k = slab * 32 + kt * 8 + (lane & 3);
    int n = nt8 * 8 + (lane >> 2);
    const float* s = src + mat * mat_off_stride + (size_t)k * ld + n;
    float4 o;
    o.x = f2tf32f(s[0] * scl);
    o.y = f2tf32f(s[(size_t)4 * ld] * scl);
    o.z = f2tf32f(s[(size_t)1 * ld] * scl);
    o.w = f2tf32f(s[(size_t)5 * ld] * scl);
    *(float4*)(dst + (size_t)gid * 4) = o;
}

// ---------------------------------------------------------------------------
// GEMM mainloop: block tile 128x128, k-slab 32, 3-stage cp.async.
// ---------------------------------------------------------------------------
#define GSTAGE_WORDS (2 * SLAB_WORDS)            // 8192
#define GEMM_SMEM_BYTES (3 * GSTAGE_WORDS * 4)   // 98304

__device__ __forceinline__ void gemm_issue_p(
    float* stage, const float* __restrict__ Ablk, const float* __restrict__ Bblk, int tid)
{
    #pragma unroll
    for (int i = 0; i < 4; i++) {
        int c = tid + i * 256;
        cp_async16(stage + c * 4, Ablk + (size_t)c * 4);
        cp_async16(stage + SLAB_WORDS + c * 4, Bblk + (size_t)c * 4);
    }
}

__device__ __forceinline__ void gemm_compute_p(
    const float* stage, float c[4][4][4], int warpM, int warpN, int lane)
{
    const uint4* A4 = (const uint4*)stage;
    const uint2* B2 = (const uint2*)(stage + SLAB_WORDS);
    #pragma unroll
    for (int kt = 0; kt < 4; kt++) {
        uint4 a[4]; uint2 b[4];
        #pragma unroll
        for (int mi = 0; mi < 4; mi++)
            a[mi] = A4[((warpM * 4 + mi) * 4 + kt) * 32 + lane];
        #pragma unroll
        for (int ni = 0; ni < 4; ni++)
            b[ni] = B2[(kt * 16 + warpN * 4 + ni) * 32 + lane];
        #pragma unroll
        for (int mi = 0; mi < 4; mi++)
            #pragma unroll
            for (int ni = 0; ni < 4; ni++)
                mma_tf32(c[mi][ni], (const unsigned*)&a[mi], (const unsigned*)&b[ni]);
    }
}

// ---------------------------------------------------------------------------
// Phase 1: QKV projection. grid = (16 heads, 32 m-tiles, 3 {Q,K,V})
// Epilogue writes tf32-rounded values (Q already pre-scaled via weights).
// ---------------------------------------------------------------------------
__global__ __launch_bounds__(256) void qkv_gemm_tc(
    const float* __restrict__ bq, const float* __restrict__ bk, const float* __restrict__ bv)
{
    extern __shared__ __align__(16) float smp[];

    const float* W; const float* bias; float* out; float bscale;
    if (blockIdx.z == 0)      { W = g_Wqp; bias = bq; out = g_Q; bscale = SCALE; }
    else if (blockIdx.z == 1) { W = g_Wkp; bias = bk; out = g_K; bscale = 1.f; }
    else                      { W = g_Wvp; bias = bv; out = g_V; bscale = 1.f; }

    const int h   = blockIdx.x;
    const int m0  = blockIdx.y * 128;
    const int tid = threadIdx.x;
    const int warp = tid >> 5, lane = tid & 31;
    const int warpM = warp >> 2, warpN = warp & 3;
    const int lq = lane >> 2, lr = lane & 3;
    const float* Ablk0 = g_Xp + (size_t)(m0 >> 7) * MAT_WORDS;
    const float* Bblk0 = W + (size_t)h * MAT_WORDS;

    float c[4][4][4];
    #pragma unroll
    for (int mi = 0; mi < 4; mi++)
        #pragma unroll
        for (int ni = 0; ni < 4; ni++)
            #pragma unroll
            for (int j = 0; j < 4; j++) c[mi][ni][j] = 0.f;

    gemm_issue_p(smp,                    Ablk0,                  Bblk0,                  tid); CP_COMMIT();
    gemm_issue_p(smp + GSTAGE_WORDS,     Ablk0 + SLAB_WORDS,     Bblk0 + SLAB_WORDS,     tid); CP_COMMIT();
    gemm_issue_p(smp + 2*GSTAGE_WORDS,   Ablk0 + 2*SLAB_WORDS,   Bblk0 + 2*SLAB_WORDS,   tid); CP_COMMIT();

    int st = 0;
    for (int s = 0; s < 64; s++) {
        float* cur = smp + st * GSTAGE_WORDS;
        CP_WAIT2();
        __syncthreads();
        gemm_compute_p(cur, c, warpM, warpN, lane);
        __syncthreads();
        if (s + 3 < 64)
            gemm_issue_p(cur, Ablk0 + (size_t)(s + 3) * SLAB_WORDS,
                              Bblk0 + (size_t)(s + 3) * SLAB_WORDS, tid);
        CP_COMMIT();
        st = (st == 2) ? 0 : st + 1;
    }

    #pragma unroll
    for (int mi = 0; mi < 4; mi++) {
        #pragma unroll
        for (int half = 0; half < 2; half++) {
            int m = m0 + warpM * 64 + mi * 16 + lq + half * 8;
            int b_ = m >> 11, sdx = m & 2047;
            float* orow = out + (((size_t)(b_ * NHEADS + h)) * SEQ + sdx) * DHEAD;
            #pragma unroll
            for (int ni = 0; ni < 4; ni++) {
                int n = warpN * 32 + ni * 8 + 2 * lr;
                float2 r;
                r.x = f2tf32f(c[mi][ni][half * 2 + 0] + bias[h * DHEAD + n]     * bscale);
                r.y = f2tf32f(c[mi][ni][half * 2 + 1] + bias[h * DHEAD + n + 1] * bscale);
                *(float2*)(orow + n) = r;
            }
        }
    }
}

// ---------------------------------------------------------------------------
// Phase 2: causal flash attention. grid = (16 pair-slots, B*H).
// Each CTA runs two q-tiles {31-i, i} (33 tiles total -> balanced).
// Staging is raw cp.async (Q/K/V pre-rounded, Q pre-scaled).
// ---------------------------------------------------------------------------
#define QP 132
#define KP 132
#define VP 136
#define PP 68
#define AOFF_KV (64*QP)
#define AOFF_P  (AOFF_KV + 64*VP)
#define AOFF_MX (AOFF_P + 64*PP)
#define AOFF_SM (AOFF_MX + 128)
#define ATT_SMEM_BYTES ((AOFF_SM + 128) * 4)   // 87040

__global__ __launch_bounds__(256, 2) void attn_tc()
{
    extern __shared__ __align__(16) unsigned smu[];
    unsigned* Qs  = smu;
    unsigned* KVs = smu + AOFF_KV;
    unsigned* Ps  = smu + AOFF_P;
    float* smax = (float*)(smu + AOFF_MX);
    float* ssum = (float*)(smu + AOFF_SM);

    const int tid = threadIdx.x;
    const int warp = tid >> 5, lane = tid & 31;
    const int warpR = warp >> 1, warpC = warp & 1;
    const int lq = lane >> 2, lr = lane & 3;
    const int bh = blockIdx.y;
    const int b  = bh >> 4, h = bh & 15;
    const int r_loc = warpR * 16 + lq;

    const float* Qg = g_Q + (size_t)(b * NHEADS + h) * SEQ * DHEAD;
    const float* Kg = g_K + (size_t)(b * NHEADS + h) * SEQ * DHEAD;
    const float* Vg = g_V + (size_t)(b * NHEADS + h) * SEQ * DHEAD;

    const int srow = tid >> 5, scc = (tid & 31) * 4;   // staging: 8 rows/iter, 16B cols

    for (int run = 0; run < 2; run++) {
        const int qt = (run == 0) ? (31 - (int)blockIdx.x) : (int)blockIdx.x;
        const int q0 = qt * 64;
        const int ntiles = qt + 1;

        // stage Q (64x128) via cp.async (safe: no other warp reads Qs here)
        #pragma unroll
        for (int i = 0; i < 8; i++) {
            int row = srow + i * 8;
            cp_async16(Qs + row * QP + scc, Qg + (size_t)(q0 + row) * DHEAD + scc);
        }
        CP_COMMIT();

        float o[8][4];
        #pragma unroll
        for (int ni = 0; ni < 8; ni++)
            #pragma unroll
            for (int j = 0; j < 4; j++) o[ni][j] = 0.f;
        float m0v = -INFINITY, m1v = -INFINITY, l0 = 0.f, l1 = 0.f;

        for (int kt = 0; kt < ntiles; kt++) {
            const int k0t = kt * 64;
            __syncthreads();   // KV free (prev PV done)
            // stage K tile via cp.async
            #pragma unroll
            for (int i = 0; i < 8; i++) {
                int row = srow + i * 8;
                cp_async16(KVs + row * KP + scc, Kg + (size_t)(k0t + row) * DHEAD + scc);
            }
            CP_COMMIT();
            CP_WAIT0();
            __syncthreads();   // K (and Q on first tile) visible

            // S = Q K^T : warp 16x32, k=128
            float s[4][4];
            #pragma unroll
            for (int ni = 0; ni < 4; ni++)
                #pragma unroll
                for (int j = 0; j < 4; j++) s[ni][j] = 0.f;

            #pragma unroll
            for (int kk = 0; kk < 128; kk += 8) {
                unsigned aq[4], bb[2];
                const int kc = kk + lr;
                aq[0] = Qs[r_loc * QP + kc];       aq[1] = Qs[(r_loc + 8) * QP + kc];
                aq[2] = Qs[r_loc * QP + kc + 4];   aq[3] = Qs[(r_loc + 8) * QP + kc + 4];
                #pragma unroll
                for (int ni = 0; ni < 4; ni++) {
                    int nb = warpC * 32 + ni * 8 + lq;
                    bb[0] = KVs[nb * KP + kc];
                    bb[1] = KVs[nb * KP + kc + 4];
                    mma_tf32(s[ni], aq, bb);
                }
            }

            const int r0g = q0 + r_loc, r1g = r0g + 8;
            float mx0 = -1e30f, mx1 = -1e30f;
            #pragma unroll
            for (int ni = 0; ni < 4; ni++) {
                int cb = k0t + warpC * 32 + ni * 8 + 2 * lr;
                if (cb     > r0g) s[ni][0] = -1e30f;
                if (cb + 1 > r0g) s[ni][1] = -1e30f;
                if (cb     > r1g) s[ni][2] = -1e30f;
                if (cb + 1 > r1g) s[ni][3] = -1e30f;
                mx0 = fmaxf(mx0, fmaxf(s[ni][0], s[ni][1]));
                mx1 = fmaxf(mx1, fmaxf(s[ni][2], s[ni][3]));
            }
            mx0 = fmaxf(mx0, __shfl_xor_sync(0xffffffffu, mx0, 1));
            mx0 = fmaxf(mx0, __shfl_xor_sync(0xffffffffu, mx0, 2));
            mx1 = fmaxf(mx1, __shfl_xor_sync(0xffffffffu, mx1, 1));
            mx1 = fmaxf(mx1, __shfl_xor_sync(0xffffffffu, mx1, 2));
            if (lr == 0) {
                smax[warpC * 64 + r_loc]     = mx0;
                smax[warpC * 64 + r_loc + 8] = mx1;
            }
            __syncthreads();   // smax visible; all K reads complete

            // issue V copy NOW (overwrites K region) so it overlaps softmax math
            #pragma unroll
            for (int i = 0; i < 8; i++) {
                int row = srow + i * 8;
                cp_async16(KVs + row * VP + scc, Vg + (size_t)(k0t + row) * DHEAD + scc);
            }
            CP_COMMIT();

            mx0 = fmaxf(mx0, smax[(warpC ^ 1) * 64 + r_loc]);
            mx1 = fmaxf(mx1, smax[(warpC ^ 1) * 64 + r_loc + 8]);

            float mn0 = fmaxf(m0v, mx0), mn1 = fmaxf(m1v, mx1);
            float ef0 = __expf(m0v - mn0), ef1 = __expf(m1v - mn1);
            m0v = mn0; m1v = mn1;

            float sum0 = 0.f, sum1 = 0.f;
            #pragma unroll
            for (int ni = 0; ni < 4; ni++) {
                float p0 = __expf(s[ni][0] - mn0);
                float p1 = __expf(s[ni][1] - mn0);
                float p2 = __expf(s[ni][2] - mn1);
                float p3 = __expf(s[ni][3] - mn1);
                sum0 += p0 + p1; sum1 += p2 + p3;
                int kc2 = warpC * 32 + ni * 8 + 2 * lr;
                Ps[r_loc * PP + kc2]           = f2tf32(p0);
                Ps[r_loc * PP + kc2 + 1]       = f2tf32(p1);
                Ps[(r_loc + 8) * PP + kc2]     = f2tf32(p2);
                Ps[(r_loc + 8) * PP + kc2 + 1] = f2tf32(p3);
            }
            sum0 += __shfl_xor_sync(0xffffffffu, sum0, 1);
            sum0 += __shfl_xor_sync(0xffffffffu, sum0, 2);
            sum1 += __shfl_xor_sync(0xffffffffu, sum1, 1);
            sum1 += __shfl_xor_sync(0xffffffffu, sum1, 2);
            if (lr == 0) {
                ssum[warpC * 64 + r_loc]     = sum0;
                ssum[warpC * 64 + r_loc + 8] = sum1;
            }
            #pragma unroll
            for (int ni = 0; ni < 8; ni++) {
                o[ni][0] *= ef0; o[ni][1] *= ef0;
                o[ni][2] *= ef1; o[ni][3] *= ef1;
            }

            CP_WAIT0();
            __syncthreads();   // V + Ps + ssum visible

            l0 = l0 * ef0 + sum0 + ssum[(warpC ^ 1) * 64 + r_loc];
            l1 = l1 * ef1 + sum1 + ssum[(warpC ^ 1) * 64 + r_loc + 8];

            // O += P @ V : warp 16x64, k=64
            #pragma unroll
            for (int kk = 0; kk < 64; kk += 8) {
                unsigned ap[4], bb[2];
                const int kc = kk + lr;
                ap[0] = Ps[r_loc * PP + kc];       ap[1] = Ps[(r_loc + 8) * PP + kc];
                ap[2] = Ps[r_loc * PP + kc + 4];   ap[3] = Ps[(r_loc + 8) * PP + kc + 4];
                #pragma unroll
                for (int ni = 0; ni < 8; ni++) {
                    int nb = warpC * 64 + ni * 8 + lq;
                    bb[0] = KVs[kc * VP + nb];
                    bb[1] = KVs[(kc + 4) * VP + nb];
                    mma_tf32(o[ni], ap, bb);
                }
            }
        }

        // normalize + scatter-write Z into A-frag permuted layout (tf32-rounded)
        float inv0 = 1.f / l0, inv1 = 1.f / l1;
        const int mglob0 = b * SEQ + q0;
        float* Zt = g_Zp + (size_t)(mglob0 >> 7) * MAT_WORDS;
        const int mrow = (mglob0 & 127) + r_loc;
        #pragma unroll
        for (int ni = 0; ni < 8; ni++) {
            int e = warpC * 64 + ni * 8 + 2 * lr;
            int kg = h * DHEAD + e;
            float* Zs = Zt + (size_t)(kg >> 5) * SLAB_WORDS;
            int kk = kg & 31;
            Zs[afrag(mrow,     kk)]     = f2tf32f(o[ni][0] * inv0);
            Zs[afrag(mrow,     kk + 1)] = f2tf32f(o[ni][1] * inv0);
            Zs[afrag(mrow + 8, kk)]     = f2tf32f(o[ni][2] * inv1);
            Zs[afrag(mrow + 8, kk + 1)] = f2tf32f(o[ni][3] * inv1);
        }
    }
}

// ---------------------------------------------------------------------------
// Phase 3: output projection. grid = (16 n-tiles, 32 m-tiles)
// ---------------------------------------------------------------------------
__global__ __launch_bounds__(256) void out_gemm_tc(
    const float* __restrict__ bO, float* __restrict__ out)
{
    extern __shared__ __align__(16) float smp[];

    const int n0  = blockIdx.x * 128;
    const int m0  = blockIdx.y * 128;
    const int tid = threadIdx.x;
    const int warp = tid >> 5, lane = tid & 31;
    const int warpM = warp >> 2, warpN = warp & 3;
    const int lq = lane >> 2, lr = lane & 3;

    const float* Ablk0 = g_Zp + (size_t)(m0 >> 7) * MAT_WORDS;
    const float* Bblk0 = g_WOp + (size_t)(n0 >> 7) * MAT_WORDS;

    float c[4][4][4];
    #pragma unroll
    for (int mi = 0; mi < 4; mi++)
        #pragma unroll
        for (int ni = 0; ni < 4; ni++)
            #pragma unroll
            for (int j = 0; j < 4; j++) c[mi][ni][j] = 0.f;

    gemm_issue_p(smp,                  Ablk0,                Bblk0,                tid); CP_COMMIT();
    gemm_issue_p(smp + GSTAGE_WORDS,   Ablk0 + SLAB_WORDS,   Bblk0 + SLAB_WORDS,   tid); CP_COMMIT();
    gemm_issue_p(smp + 2*GSTAGE_WORDS, Ablk0 + 2*SLAB_WORDS, Bblk0 + 2*SLAB_WORDS, tid); CP_COMMIT();

    int st = 0;
    for (int s = 0; s < 64; s++) {
        float* cur = smp + st * GSTAGE_WORDS;
        CP_WAIT2();
        __syncthreads();
        gemm_compute_p(cur, c, warpM, warpN, lane);
        __syncthreads();
        if (s + 3 < 64)
            gemm_issue_p(cur, Ablk0 + (size_t)(s + 3) * SLAB_WORDS,
                              Bblk0 + (size_t)(s + 3) * SLAB_WORDS, tid);
        CP_COMMIT();
        st = (st == 2) ? 0 : st + 1;
    }

    #pragma unroll
    for (int mi = 0; mi < 4; mi++) {
        #pragma unroll
        for (int half = 0; half < 2; half++) {
            int m = m0 + warpM * 64 + mi * 16 + lq + half * 8;
            float* orow = out + (size_t)m * DMODEL + n0;
            #pragma unroll
            for (int ni = 0; ni < 4; ni++) {
                int n = warpN * 32 + ni * 8 + 2 * lr;
                float2 r;
                r.x = c[mi][ni][half * 2 + 0] + bO[n0 + n];
                r.y = c[mi][ni][half * 2 + 1] + bO[n0 + n + 1];
                *(float2*)(orow + n) = r;
            }
        }
    }
}

// ---------------------------------------------------------------------------
extern "C" void kernel_launch(void* const* d_in, const int* in_sizes, int n_in,
                              void* d_out, int out_size)
{
    const float* x  = (const float*)d_in[0];
    const float* Wq = (const float*)d_in[1];
    const float* Wk = (const float*)d_in[2];
    const float* Wv = (const float*)d_in[3];
    const float* Wo = (const float*)d_in[4];
    const float* bq = (const float*)d_in[5];
    const float* bk = (const float*)d_in[6];
    const float* bv = (const float*)d_in[7];
    const float* bo = (const float*)d_in[8];
    float* out = (float*)d_out;

    float *pXp, *pWqp, *pWkp, *pWvp, *pWOp;
    cudaGetSymbolAddress((void**)&pXp,  g_Xp);
    cudaGetSymbolAddress((void**)&pWqp, g_Wqp);
    cudaGetSymbolAddress((void**)&pWkp, g_Wkp);
    cudaGetSymbolAddress((void**)&pWvp, g_Wvp);
    cudaGetSymbolAddress((void**)&pWOp, g_WOp);

    const int NXC = BATCH*SEQ*DMODEL/4;
    const int NWC = NHEADS*DMODEL*DHEAD/4;
    permute_A_kernel<<<(NXC+255)/256, 256>>>(x, pXp, NXC);
    permute_B_kernel<<<(NWC+255)/256, 256>>>(Wq, pWqp, (size_t)DMODEL*DHEAD, DHEAD, NWC, SCALE);
    permute_B_kernel<<<(NWC+255)/256, 256>>>(Wk, pWkp, (size_t)DMODEL*DHEAD, DHEAD, NWC, 1.f);
    permute_B_kernel<<<(NWC+255)/256, 256>>>(Wv, pWvp, (size_t)DMODEL*DHEAD, DHEAD, NWC, 1.f);
    permute_B_kernel<<<(NWC+255)/256, 256>>>(Wo, pWOp, (size_t)128, DMODEL, NWC, 1.f);

    dim3 blk(256);

    cudaFuncSetAttribute(qkv_gemm_tc, cudaFuncAttributeMaxDynamicSharedMemorySize, GEMM_SMEM_BYTES);
    qkv_gemm_tc<<<dim3(16, 32, 3), blk, GEMM_SMEM_BYTES>>>(bq, bk, bv);

    cudaFuncSetAttribute(attn_tc, cudaFuncAttributeMaxDynamicSharedMemorySize, ATT_SMEM_BYTES);
    attn_tc<<<dim3(16, 32), blk, ATT_SMEM_BYTES>>>();

    cudaFuncSetAttribute(out_gemm_tc, cudaFuncAttributeMaxDynamicSharedMemorySize, GEMM_SMEM_BYTES);
    out_gemm_tc<<<dim3(16, 32), blk, GEMM_SMEM_BYTES>>>(bo, out);
}